// round 14
// baseline (speedup 1.0000x reference)
#include <cuda_runtime.h>
#include <cuda_bf16.h>
#include <cstdint>

static constexpr int NTOK = 2048;
static constexpr int DIM  = 512;
static constexpr int NH   = 8;

// fp8 P-scaling: probs (~5e-4) sit below e4m3 subnormal min (1.95e-3) — R12 failure.
// Store P*1024 in fp8, divide by 1024 in the AV epilogue (exact power of 2).
static constexpr float PSCALE     = 1024.0f;
static constexpr float PSCALE_INV = 1.0f / 1024.0f;

// ---------------- scratch (allocation-free: __device__ globals) ----------------
__device__ __align__(128) __nv_bfloat16 g_bimg[(size_t)NTOK * DIM];
__device__ __align__(128) __nv_bfloat16 g_bmet[(size_t)NTOK * DIM];
__device__ __align__(128) __nv_bfloat16 g_wqm [(size_t)NH * DIM * DIM];
__device__ __align__(128) __nv_bfloat16 g_wki [(size_t)NH * DIM * DIM];
__device__ __align__(128) __nv_bfloat16 g_wvi [(size_t)NH * DIM * DIM];
__device__ __align__(128) __nv_bfloat16 g_wqi [(size_t)NH * DIM * DIM];
__device__ __align__(128) __nv_bfloat16 g_wkm [(size_t)NH * DIM * DIM];
__device__ __align__(128) __nv_bfloat16 g_wvm [(size_t)NH * DIM * DIM];
__device__ __align__(128) __nv_bfloat16 g_wli [(size_t)DIM * NH * DIM];
__device__ __align__(128) __nv_bfloat16 g_wlm [(size_t)DIM * NH * DIM];
__device__ __align__(128) uint8_t       g_qm  [(size_t)NH * NTOK * DIM];      // Q fp8
__device__ __align__(128) uint8_t       g_ki  [(size_t)NH * NTOK * DIM];      // K fp8
__device__ __align__(128) uint8_t       g_vit [(size_t)NH * DIM * NTOK];      // V_i^T fp8
__device__ __align__(128) uint8_t       g_qi  [(size_t)NH * NTOK * DIM];
__device__ __align__(128) uint8_t       g_km  [(size_t)NH * NTOK * DIM];
__device__ __align__(128) uint8_t       g_vmt [(size_t)NH * DIM * NTOK];
__device__ __align__(128) __nv_bfloat16 g_si  [(size_t)NH * NTOK * NTOK];     // scaled logits bf16
__device__ __align__(128) __nv_bfloat16 g_sm  [(size_t)NH * NTOK * NTOK];
__device__ __align__(128) uint8_t       g_pi  [(size_t)NH * NTOK * NTOK];     // probs*1024 fp8
__device__ __align__(128) uint8_t       g_pm  [(size_t)NH * NTOK * NTOK];
__device__ __align__(128) __nv_bfloat16 g_ci  [(size_t)NTOK * NH * DIM];
__device__ __align__(128) __nv_bfloat16 g_cm  [(size_t)NTOK * NH * DIM];

#define DEVINL __device__ __forceinline__

DEVINL uint32_t s2u(const void* p) { return (uint32_t)__cvta_generic_to_shared(p); }

DEVINL void ldsm4(uint32_t* r, uint32_t a) {
    asm volatile("ldmatrix.sync.aligned.m8n8.x4.shared.b16 {%0,%1,%2,%3}, [%4];"
        : "=r"(r[0]), "=r"(r[1]), "=r"(r[2]), "=r"(r[3]) : "r"(a));
}
DEVINL void mma16(float* c, const uint32_t* a, uint32_t b0, uint32_t b1) {
    asm volatile("mma.sync.aligned.m16n8k16.row.col.f32.bf16.bf16.f32 "
        "{%0,%1,%2,%3},{%4,%5,%6,%7},{%8,%9},{%0,%1,%2,%3};"
        : "+f"(c[0]), "+f"(c[1]), "+f"(c[2]), "+f"(c[3])
        : "r"(a[0]), "r"(a[1]), "r"(a[2]), "r"(a[3]), "r"(b0), "r"(b1));
}
DEVINL void mma32f8(float* c, const uint32_t* a, uint32_t b0, uint32_t b1) {
    asm volatile("mma.sync.aligned.m16n8k32.row.col.f32.e4m3.e4m3.f32 "
        "{%0,%1,%2,%3},{%4,%5,%6,%7},{%8,%9},{%0,%1,%2,%3};"
        : "+f"(c[0]), "+f"(c[1]), "+f"(c[2]), "+f"(c[3])
        : "r"(a[0]), "r"(a[1]), "r"(a[2]), "r"(a[3]), "r"(b0), "r"(b1));
}
DEVINL uint32_t pk2(float lo, float hi) {
    __nv_bfloat162 t = __floats2bfloat162_rn(lo, hi);
    return *reinterpret_cast<uint32_t*>(&t);
}
// pack 4 floats -> 4 e4m3 bytes (little-endian order v0..v3)
DEVINL uint32_t pk4f8(float v0, float v1, float v2, float v3) {
    uint16_t lo, hi;
    asm("cvt.rn.satfinite.e4m3x2.f32 %0, %1, %2;" : "=h"(lo) : "f"(v1), "f"(v0));
    asm("cvt.rn.satfinite.e4m3x2.f32 %0, %1, %2;" : "=h"(hi) : "f"(v3), "f"(v2));
    return (uint32_t)lo | ((uint32_t)hi << 16);
}
DEVINL void cp16(uint32_t dst, const void* src) {
    asm volatile("cp.async.cg.shared.global [%0], [%1], 16;" :: "r"(dst), "l"(src));
}
#define CP_COMMIT() asm volatile("cp.async.commit_group;")
#define CP_WAIT(n)  asm volatile("cp.async.wait_group %0;" :: "n"(n))

static constexpr int RPB  = 80;   // smem tile row pitch bytes: 64 data + 16 pad
static constexpr int SP   = 132;  // epilogue stage pitch (floats) — mult of 4 (R5 lesson)
static constexpr int NS   = 4;    // smem stages (2 pairs of 2 chunks)
static constexpr int TILE_B  = 128 * RPB;            // 10240 B per tile
static constexpr int STAGE_B = 2 * TILE_B;           // A+B per stage
static constexpr int SMEM_DYN = NS * STAGE_B;        // 81920 B

// --------------- per-z job descriptor (all pointers pre-offset on host) --------
// outMode: 0 fp32, 1 bf16, 2 bf16 transposed, 3 fp8, 4 fp8 transposed
struct Job {
    const char* A;
    const char* B;
    char*       C;
    const float* bias;
    const float* resid;
    float scale;
    int lda, ldb, ldc, ldr, outMode;   // lda/ldb/ldc in ELEMENTS of their dtype
};
static constexpr int MAXJ = 48;
struct Jobs { Job j[MAXJ]; };

// ---------------------------------------------------------------------------
// mma GEMM (NT), batched by z over a job table.
// F8=0: bf16 operands, K-chunk 32 elems; F8=1: e4m3 operands, K-chunk 64 elems.
// Paired-chunk pipeline: ONE wait_group + ONE barrier per 2 chunks; the next
// pair is issued right after the barrier so its cp.async overlaps both chunks'
// mma work. (Requires NC even — true for all K used here.)
// CTA 128x128, 256 thr, warp tile 64x32.
// ---------------------------------------------------------------------------
template <int F8>
__global__ __launch_bounds__(256, 2) void gemm_batch(Jobs jobs, int K)
{
    extern __shared__ __align__(128) char dsm[];
    const uint32_t sbase = s2u(dsm);
    const Job J = jobs.j[blockIdx.z];
    const int esz = F8 ? 1 : 2;

    const int tid  = threadIdx.x;
    const int warp = tid >> 5, lane = tid & 31;
    const int wm = warp & 1, wn = warp >> 1;
    const int gid = lane >> 2, tig = lane & 3;
    const int m0 = blockIdx.y * 128, n0 = blockIdx.x * 128;

    const int frow = tid & 127;
    const int fup  = (tid >> 7) * 2;          // 16B units {fup, fup+1} of the 64B row-chunk
    const char* Ap = J.A + (size_t)(m0 + frow) * J.lda * esz + fup * 16;
    const char* Bp = J.B + (size_t)(n0 + frow) * J.ldb * esz + fup * 16;
    const uint32_t sa_t = sbase + frow * RPB + fup * 16;
    const uint32_t sb_t = sa_t + TILE_B;

    const int NC = K / (F8 ? 64 : 32);
    const int NP = NC >> 1;                   // chunk pairs

    auto issue = [&](int c) {
        const uint32_t so = (uint32_t)((c & (NS - 1)) * STAGE_B);
        const char* ga = Ap + (size_t)c * 64;
        const char* gb = Bp + (size_t)c * 64;
        cp16(sa_t + so,      ga);
        cp16(sa_t + so + 16, ga + 16);
        cp16(sb_t + so,      gb);
        cp16(sb_t + so + 16, gb + 16);
    };

    float acc[4][4][4];
#pragma unroll
    for (int i = 0; i < 4; i++)
#pragma unroll
        for (int j = 0; j < 4; j++)
#pragma unroll
            for (int r = 0; r < 4; r++) acc[i][j][r] = 0.0f;

    const int lrow8  = (lane & 7) + ((lane >> 3) & 1) * 8;
    const int lchunk = (lane >> 4) * 16;
    uint32_t aoff[4], boff[2];
#pragma unroll
    for (int mt = 0; mt < 4; mt++) aoff[mt] = (uint32_t)((wm * 64 + mt * 16 + lrow8) * RPB + lchunk);
#pragma unroll
    for (int np = 0; np < 2; np++) boff[np] = (uint32_t)((wn * 32 + np * 16 + lrow8) * RPB + lchunk);

    // prologue: pair 0 in flight
    issue(0); issue(1); CP_COMMIT();

    for (int p = 0; p < NP; p++) {
        CP_WAIT(0);              // pair p arrived (only group outstanding)
        __syncthreads();         // visible to all warps; pair p-1 stages free
        if (p + 1 < NP) {        // overlap pair p+1 loads with pair p compute
            issue(2 * p + 2); issue(2 * p + 3); CP_COMMIT();
        }
#pragma unroll
        for (int cc = 0; cc < 2; cc++) {
            const int c = 2 * p + cc;
            const uint32_t so = (uint32_t)((c & (NS - 1)) * STAGE_B);
            const uint32_t ab = sbase + so;
            const uint32_t bb = ab + TILE_B;
#pragma unroll
            for (int ks = 0; ks < 2; ks++) {
                uint32_t a[4][4], b[2][4];
#pragma unroll
                for (int mt = 0; mt < 4; mt++) ldsm4(a[mt], ab + aoff[mt] + ks * 32);
#pragma unroll
                for (int np = 0; np < 2; np++) ldsm4(b[np], bb + boff[np] + ks * 32);
#pragma unroll
                for (int mt = 0; mt < 4; mt++)
#pragma unroll
                    for (int np = 0; np < 2; np++) {
                        if (F8) {
                            mma32f8(acc[mt][2 * np],     a[mt], b[np][0], b[np][2]);
                            mma32f8(acc[mt][2 * np + 1], a[mt], b[np][1], b[np][3]);
                        } else {
                            mma16(acc[mt][2 * np],     a[mt], b[np][0], b[np][2]);
                            mma16(acc[mt][2 * np + 1], a[mt], b[np][1], b[np][3]);
                        }
                    }
            }
        }
    }
    __syncthreads();

    // -------- epilogue: stage 64 m-rows at a time through smem --------
    float* stage = (float*)dsm;
    const float sc = J.scale;
    for (int p = 0; p < 2; p++) {
        if (wm == p) {
#pragma unroll
            for (int mt = 0; mt < 4; mt++) {
                const int lr = mt * 16 + gid;
#pragma unroll
                for (int nt = 0; nt < 4; nt++) {
                    const int col = wn * 32 + nt * 8 + 2 * tig;
                    *(float2*)&stage[lr * SP + col]       = make_float2(acc[mt][nt][0], acc[mt][nt][1]);
                    *(float2*)&stage[(lr + 8) * SP + col] = make_float2(acc[mt][nt][2], acc[mt][nt][3]);
                }
            }
        }
        __syncthreads();

        if (J.outMode == 0) {
            float* C = (float*)J.C;
#pragma unroll
            for (int i = 0; i < 8; i++) {
                const int idx = tid + i * 256;
                const int row = idx >> 5;
                const int c4  = (idx & 31) * 4;
                float4 v = *(float4*)&stage[row * SP + c4];
                v.x *= sc; v.y *= sc; v.z *= sc; v.w *= sc;
                const int n = n0 + c4;
                if (J.bias) { v.x += J.bias[n]; v.y += J.bias[n + 1]; v.z += J.bias[n + 2]; v.w += J.bias[n + 3]; }
                const int m = m0 + p * 64 + row;
                if (J.resid) {
                    float4 rr = *(const float4*)(J.resid + (size_t)m * J.ldr + n);
                    v.x += rr.x; v.y += rr.y; v.z += rr.z; v.w += rr.w;
                }
                *(float4*)(C + (size_t)m * J.ldc + n) = v;
            }
        } else if (J.outMode == 1) {
            __nv_bfloat16* C = (__nv_bfloat16*)J.C;
#pragma unroll
            for (int i = 0; i < 8; i++) {
                const int idx = tid + i * 256;
                const int row = idx >> 5;
                const int c4  = (idx & 31) * 4;
                float4 v = *(float4*)&stage[row * SP + c4];
                v.x *= sc; v.y *= sc; v.z *= sc; v.w *= sc;
                const int n = n0 + c4;
                if (J.bias) { v.x += J.bias[n]; v.y += J.bias[n + 1]; v.z += J.bias[n + 2]; v.w += J.bias[n + 3]; }
                uint2 o = make_uint2(pk2(v.x, v.y), pk2(v.z, v.w));
                *(uint2*)(C + (size_t)(m0 + p * 64 + row) * J.ldc + n) = o;
            }
        } else if (J.outMode == 2) {
            __nv_bfloat16* C = (__nv_bfloat16*)J.C;
#pragma unroll
            for (int i = 0; i < 8; i++) {
                const int idx = tid + i * 256;
                const int mq  = (idx & 15) * 4;
                const int col = idx >> 4;
                const float bv = J.bias ? J.bias[n0 + col] : 0.0f;
                float f0 = stage[(mq + 0) * SP + col] * sc + bv;
                float f1 = stage[(mq + 1) * SP + col] * sc + bv;
                float f2 = stage[(mq + 2) * SP + col] * sc + bv;
                float f3 = stage[(mq + 3) * SP + col] * sc + bv;
                uint2 o = make_uint2(pk2(f0, f1), pk2(f2, f3));
                *(uint2*)(C + (size_t)(n0 + col) * J.ldc + m0 + p * 64 + mq) = o;
            }
        } else if (J.outMode == 3) {
            uint8_t* C = (uint8_t*)J.C;
#pragma unroll
            for (int i = 0; i < 8; i++) {
                const int idx = tid + i * 256;
                const int row = idx >> 5;
                const int c4  = (idx & 31) * 4;
                float4 v = *(float4*)&stage[row * SP + c4];
                v.x *= sc; v.y *= sc; v.z *= sc; v.w *= sc;
                const int n = n0 + c4;
                if (J.bias) { v.x += J.bias[n]; v.y += J.bias[n + 1]; v.z += J.bias[n + 2]; v.w += J.bias[n + 3]; }
                *(uint32_t*)(C + (size_t)(m0 + p * 64 + row) * J.ldc + n) = pk4f8(v.x, v.y, v.z, v.w);
            }
        } else {
            uint8_t* C = (uint8_t*)J.C;
#pragma unroll
            for (int i = 0; i < 8; i++) {
                const int idx = tid + i * 256;
                const int mq  = (idx & 15) * 4;
                const int col = idx >> 4;
                const float bv = J.bias ? J.bias[n0 + col] : 0.0f;
                float f0 = stage[(mq + 0) * SP + col] * sc + bv;
                float f1 = stage[(mq + 1) * SP + col] * sc + bv;
                float f2 = stage[(mq + 2) * SP + col] * sc + bv;
                float f3 = stage[(mq + 3) * SP + col] * sc + bv;
                *(uint32_t*)(C + (size_t)(n0 + col) * J.ldc + m0 + p * 64 + mq) = pk4f8(f0, f1, f2, f3);
            }
        }
        __syncthreads();
    }
}

// ---------------------------------------------------------------------------
// fp32 -> bf16 bulk convert, 10 tensors in one launch (grid.y = tensor idx)
// ---------------------------------------------------------------------------
struct CvtJobs { const float* s[10]; __nv_bfloat16* d[10]; int n[10]; };

__global__ __launch_bounds__(256) void cvt_bf(CvtJobs j)
{
    const int t = blockIdx.y;
    const float* src = j.s[t];
    __nv_bfloat16* dst = j.d[t];
    const int n = j.n[t];
    const int stride = gridDim.x * blockDim.x * 4;
    for (int i = (blockIdx.x * blockDim.x + threadIdx.x) * 4; i < n; i += stride) {
        float4 v = *(const float4*)(src + i);
        uint2 o = make_uint2(pk2(v.x, v.y), pk2(v.z, v.w));
        *(uint2*)(dst + i) = o;
    }
}

// ---------------------------------------------------------------------------
// Row softmax (2048 cols): bf16 scaled logits in -> fp8 e4m3 probs*PSCALE out.
// No max-subtraction: logits bounded (|x| ≲ 3), softmax shift-invariant.
// ---------------------------------------------------------------------------
__global__ __launch_bounds__(256) void softmax_bf(
    const __nv_bfloat16* __restrict__ S0, uint8_t* __restrict__ P0,
    const __nv_bfloat16* __restrict__ S1, uint8_t* __restrict__ P1)
{
    const __nv_bfloat16* S = blockIdx.y ? S1 : S0;
    uint8_t* P = blockIdx.y ? P1 : P0;
    const __nv_bfloat16* row = S + (size_t)blockIdx.x * NTOK;
    uint8_t* prow = P + (size_t)blockIdx.x * NTOK;
    const int tid = threadIdx.x;

    uint4 u = *(const uint4*)(row + tid * 8);
    float v[8];
    {
        const uint32_t w[4] = {u.x, u.y, u.z, u.w};
#pragma unroll
        for (int q = 0; q < 4; q++) {
            __nv_bfloat162 t = *reinterpret_cast<const __nv_bfloat162*>(&w[q]);
            float2 f = __bfloat1622float2(t);
            v[2 * q] = f.x; v[2 * q + 1] = f.y;
        }
    }

    float sum = 0.0f;
#pragma unroll
    for (int i = 0; i < 8; i++) { v[i] = __expf(v[i]); sum += v[i]; }

    __shared__ float red[8];
#pragma unroll
    for (int o = 16; o; o >>= 1) sum += __shfl_xor_sync(0xffffffffu, sum, o);
    if ((tid & 31) == 0) red[tid >> 5] = sum;
    __syncthreads();
    sum = red[0];
#pragma unroll
    for (int i = 1; i < 8; i++) sum += red[i];

    const float inv = PSCALE / sum;   // fold fp8 range-scaling into normalization
    uint32_t o0 = pk4f8(v[0] * inv, v[1] * inv, v[2] * inv, v[3] * inv);
    uint32_t o1 = pk4f8(v[4] * inv, v[5] * inv, v[6] * inv, v[7] * inv);
    *(uint2*)(prow + tid * 8) = make_uint2(o0, o1);
}

// ---------------------------------------------------------------------------
extern "C" void kernel_launch(void* const* d_in, const int* in_sizes, int n_in,
                              void* d_out, int out_size)
{
    (void)in_sizes; (void)n_in; (void)out_size;

    const float* image = (const float*)d_in[0];
    const float* meta  = (const float*)d_in[1];
    const float* Wq_m  = (const float*)d_in[2];  const float* bq_m = (const float*)d_in[3];
    const float* Wk_i  = (const float*)d_in[4];  const float* bk_i = (const float*)d_in[5];
    const float* Wv_i  = (const float*)d_in[6];  const float* bv_i = (const float*)d_in[7];
    const float* Wq_i  = (const float*)d_in[8];  const float* bq_i = (const float*)d_in[9];
    const float* Wk_m  = (const float*)d_in[10]; const float* bk_m = (const float*)d_in[11];
    const float* Wv_m  = (const float*)d_in[12]; const float* bv_m = (const float*)d_in[13];
    const float* Wli   = (const float*)d_in[14]; const float* bli  = (const float*)d_in[15];
    const float* Wlm   = (const float*)d_in[16]; const float* blm  = (const float*)d_in[17];
    float* out = (float*)d_out;

    __nv_bfloat16 *bimg, *bmet, *wqm, *wki, *wvi, *wqi, *wkm, *wvm, *wli, *wlm;
    __nv_bfloat16 *si, *sm, *ci, *cm;
    uint8_t *qm, *ki, *vit, *qi, *km, *vmt, *pi, *pm;
    cudaGetSymbolAddress((void**)&bimg, g_bimg);
    cudaGetSymbolAddress((void**)&bmet, g_bmet);
    cudaGetSymbolAddress((void**)&wqm,  g_wqm);
    cudaGetSymbolAddress((void**)&wki,  g_wki);
    cudaGetSymbolAddress((void**)&wvi,  g_wvi);
    cudaGetSymbolAddress((void**)&wqi,  g_wqi);
    cudaGetSymbolAddress((void**)&wkm,  g_wkm);
    cudaGetSymbolAddress((void**)&wvm,  g_wvm);
    cudaGetSymbolAddress((void**)&wli,  g_wli);
    cudaGetSymbolAddress((void**)&wlm,  g_wlm);
    cudaGetSymbolAddress((void**)&qm,   g_qm);
    cudaGetSymbolAddress((void**)&ki,   g_ki);
    cudaGetSymbolAddress((void**)&vit,  g_vit);
    cudaGetSymbolAddress((void**)&qi,   g_qi);
    cudaGetSymbolAddress((void**)&km,   g_km);
    cudaGetSymbolAddress((void**)&vmt,  g_vmt);
    cudaGetSymbolAddress((void**)&si,   g_si);
    cudaGetSymbolAddress((void**)&sm,   g_sm);
    cudaGetSymbolAddress((void**)&pi,   g_pi);
    cudaGetSymbolAddress((void**)&pm,   g_pm);
    cudaGetSymbolAddress((void**)&ci,   g_ci);
    cudaGetSymbolAddress((void**)&cm,   g_cm);

    cudaFuncSetAttribute(gemm_batch<0>, cudaFuncAttributeMaxDynamicSharedMemorySize, SMEM_DYN);
    cudaFuncSetAttribute(gemm_batch<1>, cudaFuncAttributeMaxDynamicSharedMemorySize, SMEM_DYN);

    // ---- pre-convert all fp32 operands to bf16 (one launch)
    {
        CvtJobs j;
        const int nW = NH * DIM * DIM;
        const int nL = DIM * NH * DIM;
        const int nX = NTOK * DIM;
        j.s[0] = image; j.d[0] = bimg; j.n[0] = nX;
        j.s[1] = meta;  j.d[1] = bmet; j.n[1] = nX;
        j.s[2] = Wq_m;  j.d[2] = wqm;  j.n[2] = nW;
        j.s[3] = Wk_i;  j.d[3] = wki;  j.n[3] = nW;
        j.s[4] = Wv_i;  j.d[4] = wvi;  j.n[4] = nW;
        j.s[5] = Wq_i;  j.d[5] = wqi;  j.n[5] = nW;
        j.s[6] = Wk_m;  j.d[6] = wkm;  j.n[6] = nW;
        j.s[7] = Wv_m;  j.d[7] = wvm;  j.n[7] = nW;
        j.s[8] = Wli;   j.d[8] = wli;  j.n[8] = nL;
        j.s[9] = Wlm;   j.d[9] = wlm;  j.n[9] = nL;
        cvt_bf<<<dim3(1024, 10), 256>>>(j);
    }

    const dim3 blk(256);
    const size_t sW  = (size_t)DIM * DIM;
    const size_t sO  = (size_t)NTOK * DIM;
    const size_t sOT = (size_t)DIM * NTOK;
    const size_t sS  = (size_t)NTOK * NTOK;
    const float scale = 0.04419417382415922f;   // 1/sqrt(512)

    // ---- projections (bf16 in): ONE launch, 48 jobs; Q/K -> fp8, V -> fp8^T
    {
        Jobs jb;
        const __nv_bfloat16* As[6]  = {bmet, bimg, bimg, bimg, bmet, bmet};
        const __nv_bfloat16* Ws[6]  = {wqm,  wki,  wvi,  wqi,  wkm,  wvm};
        uint8_t*             Cs[6]  = {qm,   ki,   vit,  qi,   km,   vmt};
        const float*         Bs[6]  = {bq_m, bk_i, bv_i, bq_i, bk_m, bv_m};
        const int            md[6]  = {3, 3, 4, 3, 3, 4};
        for (int g = 0; g < 6; g++)
            for (int h = 0; h < NH; h++) {
                Job& J = jb.j[g * NH + h];
                J.A = (const char*)As[g];
                J.B = (const char*)(Ws[g] + (size_t)h * sW);
                J.C = (char*)(Cs[g] + (md[g] == 4 ? (size_t)h * sOT : (size_t)h * sO));
                J.bias = Bs[g] + (size_t)h * DIM;
                J.resid = nullptr;
                J.scale = 1.0f;
                J.lda = DIM; J.ldb = DIM;
                J.ldc = (md[g] == 4) ? NTOK : DIM;
                J.ldr = 0; J.outMode = md[g];
            }
        gemm_batch<0><<<dim3(DIM / 128, NTOK / 128, 48), blk, SMEM_DYN>>>(jb, DIM);
    }

    // ---- scores (fp8 in): ONE launch, 16 jobs, bf16 pre-scaled logits out
    {
        Jobs jb;
        for (int p = 0; p < 2; p++)
            for (int h = 0; h < NH; h++) {
                Job& J = jb.j[p * NH + h];
                J.A = (const char*)((p ? qi : qm) + (size_t)h * sO);
                J.B = (const char*)((p ? km : ki) + (size_t)h * sO);
                J.C = (char*)((p ? sm : si) + (size_t)h * sS);
                J.bias = nullptr; J.resid = nullptr;
                J.scale = scale;
                J.lda = DIM; J.ldb = DIM; J.ldc = NTOK; J.ldr = 0; J.outMode = 1;
            }
        gemm_batch<1><<<dim3(NTOK / 128, NTOK / 128, 16), blk, SMEM_DYN>>>(jb, DIM);
    }

    // ---- softmax (both directions): bf16 logits -> fp8 probs*PSCALE
    softmax_bf<<<dim3(NH * NTOK, 2), 256>>>(si, pi, sm, pm);

    // ---- AV (fp8 in): ONE launch, 16 jobs -> concat [2048, 4096] bf16, /PSCALE
    {
        Jobs jb;
        for (int p = 0; p < 2; p++)
            for (int h = 0; h < NH; h++) {
                Job& J = jb.j[p * NH + h];
                J.A = (const char*)((p ? pm : pi) + (size_t)h * sS);
                J.B = (const char*)((p ? vmt : vit) + (size_t)h * sOT);
                J.C = (char*)((p ? cm : ci) + (size_t)h * DIM);
                J.bias = nullptr; J.resid = nullptr;
                J.scale = PSCALE_INV;
                J.lda = NTOK; J.ldb = NTOK; J.ldc = NH * DIM; J.ldr = 0; J.outMode = 1;
            }
        gemm_batch<1><<<dim3(DIM / 128, NTOK / 128, 16), blk, SMEM_DYN>>>(jb, NTOK);
    }

    // ---- final linears (bf16 in): ONE launch, 2 jobs, bias + fp32 residual -> d_out
    {
        Jobs jb;
        jb.j[0] = { (const char*)ci, (const char*)wli, (char*)out,
                    bli, image, 1.0f, NH * DIM, NH * DIM, 2 * DIM, DIM, 0 };
        jb.j[1] = { (const char*)cm, (const char*)wlm, (char*)(out + DIM),
                    blm, meta,  1.0f, NH * DIM, NH * DIM, 2 * DIM, DIM, 0 };
        gemm_batch<0><<<dim3(DIM / 128, NTOK / 128, 2), blk, SMEM_DYN>>>(jb, NH * DIM);
    }
}

// round 15
// speedup vs baseline: 1.0432x; 1.0432x over previous
#include <cuda_runtime.h>
#include <cuda_bf16.h>
#include <cstdint>

static constexpr int NTOK = 2048;
static constexpr int DIM  = 512;
static constexpr int NH   = 8;

// fp8 P-scaling: probs (~5e-4) sit below e4m3 subnormal min (1.95e-3) — R12 failure.
// Store P*1024 in fp8, divide by 1024 in the AV epilogue (exact power of 2).
static constexpr float PSCALE     = 1024.0f;
static constexpr float PSCALE_INV = 1.0f / 1024.0f;

// ---------------- scratch (allocation-free: __device__ globals) ----------------
__device__ __align__(128) __nv_bfloat16 g_bimg[(size_t)NTOK * DIM];
__device__ __align__(128) __nv_bfloat16 g_bmet[(size_t)NTOK * DIM];
__device__ __align__(128) __nv_bfloat16 g_wqm [(size_t)NH * DIM * DIM];
__device__ __align__(128) __nv_bfloat16 g_wki [(size_t)NH * DIM * DIM];
__device__ __align__(128) __nv_bfloat16 g_wvi [(size_t)NH * DIM * DIM];
__device__ __align__(128) __nv_bfloat16 g_wqi [(size_t)NH * DIM * DIM];
__device__ __align__(128) __nv_bfloat16 g_wkm [(size_t)NH * DIM * DIM];
__device__ __align__(128) __nv_bfloat16 g_wvm [(size_t)NH * DIM * DIM];
__device__ __align__(128) __nv_bfloat16 g_wli [(size_t)DIM * NH * DIM];
__device__ __align__(128) __nv_bfloat16 g_wlm [(size_t)DIM * NH * DIM];
__device__ __align__(128) uint8_t       g_qm  [(size_t)NH * NTOK * DIM];      // Q fp8
__device__ __align__(128) uint8_t       g_ki  [(size_t)NH * NTOK * DIM];      // K fp8
__device__ __align__(128) uint8_t       g_vit [(size_t)NH * DIM * NTOK];      // V_i^T fp8
__device__ __align__(128) uint8_t       g_qi  [(size_t)NH * NTOK * DIM];
__device__ __align__(128) uint8_t       g_km  [(size_t)NH * NTOK * DIM];
__device__ __align__(128) uint8_t       g_vmt [(size_t)NH * DIM * NTOK];
__device__ __align__(128) __nv_bfloat16 g_si  [(size_t)NH * NTOK * NTOK];     // scaled logits bf16
__device__ __align__(128) __nv_bfloat16 g_sm  [(size_t)NH * NTOK * NTOK];
__device__ __align__(128) uint8_t       g_pi  [(size_t)NH * NTOK * NTOK];     // probs*1024 fp8
__device__ __align__(128) uint8_t       g_pm  [(size_t)NH * NTOK * NTOK];
__device__ __align__(128) __nv_bfloat16 g_ci  [(size_t)NTOK * NH * DIM];
__device__ __align__(128) __nv_bfloat16 g_cm  [(size_t)NTOK * NH * DIM];

#define DEVINL __device__ __forceinline__

DEVINL uint32_t s2u(const void* p) { return (uint32_t)__cvta_generic_to_shared(p); }

DEVINL void ldsm4(uint32_t* r, uint32_t a) {
    asm volatile("ldmatrix.sync.aligned.m8n8.x4.shared.b16 {%0,%1,%2,%3}, [%4];"
        : "=r"(r[0]), "=r"(r[1]), "=r"(r[2]), "=r"(r[3]) : "r"(a));
}
DEVINL void mma16(float* c, const uint32_t* a, uint32_t b0, uint32_t b1) {
    asm volatile("mma.sync.aligned.m16n8k16.row.col.f32.bf16.bf16.f32 "
        "{%0,%1,%2,%3},{%4,%5,%6,%7},{%8,%9},{%0,%1,%2,%3};"
        : "+f"(c[0]), "+f"(c[1]), "+f"(c[2]), "+f"(c[3])
        : "r"(a[0]), "r"(a[1]), "r"(a[2]), "r"(a[3]), "r"(b0), "r"(b1));
}
DEVINL void mma32f8(float* c, const uint32_t* a, uint32_t b0, uint32_t b1) {
    asm volatile("mma.sync.aligned.m16n8k32.row.col.f32.e4m3.e4m3.f32 "
        "{%0,%1,%2,%3},{%4,%5,%6,%7},{%8,%9},{%0,%1,%2,%3};"
        : "+f"(c[0]), "+f"(c[1]), "+f"(c[2]), "+f"(c[3])
        : "r"(a[0]), "r"(a[1]), "r"(a[2]), "r"(a[3]), "r"(b0), "r"(b1));
}
DEVINL uint32_t pk2(float lo, float hi) {
    __nv_bfloat162 t = __floats2bfloat162_rn(lo, hi);
    return *reinterpret_cast<uint32_t*>(&t);
}
// pack 4 floats -> 4 e4m3 bytes (little-endian order v0..v3)
DEVINL uint32_t pk4f8(float v0, float v1, float v2, float v3) {
    uint16_t lo, hi;
    asm("cvt.rn.satfinite.e4m3x2.f32 %0, %1, %2;" : "=h"(lo) : "f"(v1), "f"(v0));
    asm("cvt.rn.satfinite.e4m3x2.f32 %0, %1, %2;" : "=h"(hi) : "f"(v3), "f"(v2));
    return (uint32_t)lo | ((uint32_t)hi << 16);
}
DEVINL void cp16(uint32_t dst, const void* src) {
    asm volatile("cp.async.cg.shared.global [%0], [%1], 16;" :: "r"(dst), "l"(src));
}
#define CP_COMMIT() asm volatile("cp.async.commit_group;")
#define CP_WAIT(n)  asm volatile("cp.async.wait_group %0;" :: "n"(n))

static constexpr int RPB  = 80;   // smem tile row pitch bytes: 64 data + 16 pad
static constexpr int SP   = 132;  // epilogue stage pitch (floats) — mult of 4 (R5 lesson)
static constexpr int NS   = 4;    // cp.async pipeline stages (R13 scheme — R14 pairing regressed)
static constexpr int TILE_B  = 128 * RPB;            // 10240 B per tile
static constexpr int STAGE_B = 2 * TILE_B;           // A+B per stage
static constexpr int SMEM_DYN = NS * STAGE_B;        // 81920 B

// --------------- per-z job descriptor (all pointers pre-offset on host) --------
// outMode: 0 fp32, 1 bf16, 2 bf16 transposed, 3 fp8, 4 fp8 transposed
struct Job {
    const char* A;
    const char* B;
    char*       C;
    const float* bias;
    const float* resid;
    float scale;
    int lda, ldb, ldc, ldr, outMode;   // lda/ldb/ldc in ELEMENTS of their dtype
};
static constexpr int MAXJ = 48;
struct Jobs { Job j[MAXJ]; };

// ---------------------------------------------------------------------------
// mma GEMM (NT), batched by z over a job table.  (R13 pipeline — converged.)
// F8=0: bf16 operands, K-chunk 32 elems; F8=1: e4m3 operands, K-chunk 64 elems.
// CTA 128x128, 256 thr, warp tile 64x32, 4-stage cp.async, wait(NS-2)/chunk.
// ---------------------------------------------------------------------------
template <int F8>
__global__ __launch_bounds__(256, 2) void gemm_batch(Jobs jobs, int K)
{
    extern __shared__ __align__(128) char dsm[];
    const uint32_t sbase = s2u(dsm);
    const Job J = jobs.j[blockIdx.z];
    const int esz = F8 ? 1 : 2;

    const int tid  = threadIdx.x;
    const int warp = tid >> 5, lane = tid & 31;
    const int wm = warp & 1, wn = warp >> 1;
    const int gid = lane >> 2, tig = lane & 3;
    const int m0 = blockIdx.y * 128, n0 = blockIdx.x * 128;

    const int frow = tid & 127;
    const int fup  = (tid >> 7) * 2;          // 16B units {fup, fup+1} of the 64B row-chunk
    const char* Ap = J.A + (size_t)(m0 + frow) * J.lda * esz + fup * 16;
    const char* Bp = J.B + (size_t)(n0 + frow) * J.ldb * esz + fup * 16;
    const uint32_t sa_t = sbase + frow * RPB + fup * 16;
    const uint32_t sb_t = sa_t + TILE_B;

    const int NC = K / (F8 ? 64 : 32);

    auto issue = [&](int c) {
        const uint32_t so = (uint32_t)((c & (NS - 1)) * STAGE_B);
        const char* ga = Ap + (size_t)c * 64;
        const char* gb = Bp + (size_t)c * 64;
        cp16(sa_t + so,      ga);
        cp16(sa_t + so + 16, ga + 16);
        cp16(sb_t + so,      gb);
        cp16(sb_t + so + 16, gb + 16);
    };

    float acc[4][4][4];
#pragma unroll
    for (int i = 0; i < 4; i++)
#pragma unroll
        for (int j = 0; j < 4; j++)
#pragma unroll
            for (int r = 0; r < 4; r++) acc[i][j][r] = 0.0f;

    const int lrow8  = (lane & 7) + ((lane >> 3) & 1) * 8;
    const int lchunk = (lane >> 4) * 16;
    uint32_t aoff[4], boff[2];
#pragma unroll
    for (int mt = 0; mt < 4; mt++) aoff[mt] = (uint32_t)((wm * 64 + mt * 16 + lrow8) * RPB + lchunk);
#pragma unroll
    for (int np = 0; np < 2; np++) boff[np] = (uint32_t)((wn * 32 + np * 16 + lrow8) * RPB + lchunk);

#pragma unroll
    for (int c = 0; c < NS - 1; c++) {
        if (c < NC) issue(c);
        CP_COMMIT();
    }

    for (int c = 0; c < NC; c++) {
        CP_WAIT(NS - 2);
        __syncthreads();
        if (c + NS - 1 < NC) issue(c + NS - 1);
        CP_COMMIT();

        const uint32_t so = (uint32_t)((c & (NS - 1)) * STAGE_B);
        const uint32_t ab = sbase + so;
        const uint32_t bb = ab + TILE_B;
#pragma unroll
        for (int ks = 0; ks < 2; ks++) {
            uint32_t a[4][4], b[2][4];
#pragma unroll
            for (int mt = 0; mt < 4; mt++) ldsm4(a[mt], ab + aoff[mt] + ks * 32);
#pragma unroll
            for (int np = 0; np < 2; np++) ldsm4(b[np], bb + boff[np] + ks * 32);
#pragma unroll
            for (int mt = 0; mt < 4; mt++)
#pragma unroll
                for (int np = 0; np < 2; np++) {
                    if (F8) {
                        mma32f8(acc[mt][2 * np],     a[mt], b[np][0], b[np][2]);
                        mma32f8(acc[mt][2 * np + 1], a[mt], b[np][1], b[np][3]);
                    } else {
                        mma16(acc[mt][2 * np],     a[mt], b[np][0], b[np][2]);
                        mma16(acc[mt][2 * np + 1], a[mt], b[np][1], b[np][3]);
                    }
                }
        }
    }
    CP_WAIT(0);
    __syncthreads();

    // -------- epilogue: stage 64 m-rows at a time through smem --------
    float* stage = (float*)dsm;
    const float sc = J.scale;
    for (int p = 0; p < 2; p++) {
        if (wm == p) {
#pragma unroll
            for (int mt = 0; mt < 4; mt++) {
                const int lr = mt * 16 + gid;
#pragma unroll
                for (int nt = 0; nt < 4; nt++) {
                    const int col = wn * 32 + nt * 8 + 2 * tig;
                    *(float2*)&stage[lr * SP + col]       = make_float2(acc[mt][nt][0], acc[mt][nt][1]);
                    *(float2*)&stage[(lr + 8) * SP + col] = make_float2(acc[mt][nt][2], acc[mt][nt][3]);
                }
            }
        }
        __syncthreads();

        if (J.outMode == 0) {
            float* C = (float*)J.C;
#pragma unroll
            for (int i = 0; i < 8; i++) {
                const int idx = tid + i * 256;
                const int row = idx >> 5;
                const int c4  = (idx & 31) * 4;
                float4 v = *(float4*)&stage[row * SP + c4];
                v.x *= sc; v.y *= sc; v.z *= sc; v.w *= sc;
                const int n = n0 + c4;
                if (J.bias) { v.x += J.bias[n]; v.y += J.bias[n + 1]; v.z += J.bias[n + 2]; v.w += J.bias[n + 3]; }
                const int m = m0 + p * 64 + row;
                if (J.resid) {
                    float4 rr = *(const float4*)(J.resid + (size_t)m * J.ldr + n);
                    v.x += rr.x; v.y += rr.y; v.z += rr.z; v.w += rr.w;
                }
                *(float4*)(C + (size_t)m * J.ldc + n) = v;
            }
        } else if (J.outMode == 1) {
            __nv_bfloat16* C = (__nv_bfloat16*)J.C;
#pragma unroll
            for (int i = 0; i < 8; i++) {
                const int idx = tid + i * 256;
                const int row = idx >> 5;
                const int c4  = (idx & 31) * 4;
                float4 v = *(float4*)&stage[row * SP + c4];
                v.x *= sc; v.y *= sc; v.z *= sc; v.w *= sc;
                const int n = n0 + c4;
                if (J.bias) { v.x += J.bias[n]; v.y += J.bias[n + 1]; v.z += J.bias[n + 2]; v.w += J.bias[n + 3]; }
                uint2 o = make_uint2(pk2(v.x, v.y), pk2(v.z, v.w));
                *(uint2*)(C + (size_t)(m0 + p * 64 + row) * J.ldc + n) = o;
            }
        } else if (J.outMode == 2) {
            __nv_bfloat16* C = (__nv_bfloat16*)J.C;
#pragma unroll
            for (int i = 0; i < 8; i++) {
                const int idx = tid + i * 256;
                const int mq  = (idx & 15) * 4;
                const int col = idx >> 4;
                const float bv = J.bias ? J.bias[n0 + col] : 0.0f;
                float f0 = stage[(mq + 0) * SP + col] * sc + bv;
                float f1 = stage[(mq + 1) * SP + col] * sc + bv;
                float f2 = stage[(mq + 2) * SP + col] * sc + bv;
                float f3 = stage[(mq + 3) * SP + col] * sc + bv;
                uint2 o = make_uint2(pk2(f0, f1), pk2(f2, f3));
                *(uint2*)(C + (size_t)(n0 + col) * J.ldc + m0 + p * 64 + mq) = o;
            }
        } else if (J.outMode == 3) {
            uint8_t* C = (uint8_t*)J.C;
#pragma unroll
            for (int i = 0; i < 8; i++) {
                const int idx = tid + i * 256;
                const int row = idx >> 5;
                const int c4  = (idx & 31) * 4;
                float4 v = *(float4*)&stage[row * SP + c4];
                v.x *= sc; v.y *= sc; v.z *= sc; v.w *= sc;
                const int n = n0 + c4;
                if (J.bias) { v.x += J.bias[n]; v.y += J.bias[n + 1]; v.z += J.bias[n + 2]; v.w += J.bias[n + 3]; }
                *(uint32_t*)(C + (size_t)(m0 + p * 64 + row) * J.ldc + n) = pk4f8(v.x, v.y, v.z, v.w);
            }
        } else {
            uint8_t* C = (uint8_t*)J.C;
#pragma unroll
            for (int i = 0; i < 8; i++) {
                const int idx = tid + i * 256;
                const int mq  = (idx & 15) * 4;
                const int col = idx >> 4;
                const float bv = J.bias ? J.bias[n0 + col] : 0.0f;
                float f0 = stage[(mq + 0) * SP + col] * sc + bv;
                float f1 = stage[(mq + 1) * SP + col] * sc + bv;
                float f2 = stage[(mq + 2) * SP + col] * sc + bv;
                float f3 = stage[(mq + 3) * SP + col] * sc + bv;
                *(uint32_t*)(C + (size_t)(n0 + col) * J.ldc + m0 + p * 64 + mq) = pk4f8(f0, f1, f2, f3);
            }
        }
        __syncthreads();
    }
}

// ---------------------------------------------------------------------------
// fp32 -> bf16 bulk convert, 10 tensors in one launch (grid.y = tensor idx)
// ---------------------------------------------------------------------------
struct CvtJobs { const float* s[10]; __nv_bfloat16* d[10]; int n[10]; };

__global__ __launch_bounds__(256) void cvt_bf(CvtJobs j)
{
    const int t = blockIdx.y;
    const float* src = j.s[t];
    __nv_bfloat16* dst = j.d[t];
    const int n = j.n[t];
    const int stride = gridDim.x * blockDim.x * 4;
    for (int i = (blockIdx.x * blockDim.x + threadIdx.x) * 4; i < n; i += stride) {
        float4 v = *(const float4*)(src + i);
        uint2 o = make_uint2(pk2(v.x, v.y), pk2(v.z, v.w));
        *(uint2*)(dst + i) = o;
    }
}

// ---------------------------------------------------------------------------
// Row softmax (2048 cols): bf16 scaled logits in -> fp8 e4m3 probs*PSCALE out.
// No max-subtraction: logits bounded (|x| ≲ 3), softmax shift-invariant (R14-validated).
// ---------------------------------------------------------------------------
__global__ __launch_bounds__(256) void softmax_bf(
    const __nv_bfloat16* __restrict__ S0, uint8_t* __restrict__ P0,
    const __nv_bfloat16* __restrict__ S1, uint8_t* __restrict__ P1)
{
    const __nv_bfloat16* S = blockIdx.y ? S1 : S0;
    uint8_t* P = blockIdx.y ? P1 : P0;
    const __nv_bfloat16* row = S + (size_t)blockIdx.x * NTOK;
    uint8_t* prow = P + (size_t)blockIdx.x * NTOK;
    const int tid = threadIdx.x;

    uint4 u = *(const uint4*)(row + tid * 8);
    float v[8];
    {
        const uint32_t w[4] = {u.x, u.y, u.z, u.w};
#pragma unroll
        for (int q = 0; q < 4; q++) {
            __nv_bfloat162 t = *reinterpret_cast<const __nv_bfloat162*>(&w[q]);
            float2 f = __bfloat1622float2(t);
            v[2 * q] = f.x; v[2 * q + 1] = f.y;
        }
    }

    float sum = 0.0f;
#pragma unroll
    for (int i = 0; i < 8; i++) { v[i] = __expf(v[i]); sum += v[i]; }

    __shared__ float red[8];
#pragma unroll
    for (int o = 16; o; o >>= 1) sum += __shfl_xor_sync(0xffffffffu, sum, o);
    if ((tid & 31) == 0) red[tid >> 5] = sum;
    __syncthreads();
    sum = red[0];
#pragma unroll
    for (int i = 1; i < 8; i++) sum += red[i];

    const float inv = PSCALE / sum;   // fold fp8 range-scaling into normalization
    uint32_t o0 = pk4f8(v[0] * inv, v[1] * inv, v[2] * inv, v[3] * inv);
    uint32_t o1 = pk4f8(v[4] * inv, v[5] * inv, v[6] * inv, v[7] * inv);
    *(uint2*)(prow + tid * 8) = make_uint2(o0, o1);
}

// ---------------------------------------------------------------------------
extern "C" void kernel_launch(void* const* d_in, const int* in_sizes, int n_in,
                              void* d_out, int out_size)
{
    (void)in_sizes; (void)n_in; (void)out_size;

    const float* image = (const float*)d_in[0];
    const float* meta  = (const float*)d_in[1];
    const float* Wq_m  = (const float*)d_in[2];  const float* bq_m = (const float*)d_in[3];
    const float* Wk_i  = (const float*)d_in[4];  const float* bk_i = (const float*)d_in[5];
    const float* Wv_i  = (const float*)d_in[6];  const float* bv_i = (const float*)d_in[7];
    const float* Wq_i  = (const float*)d_in[8];  const float* bq_i = (const float*)d_in[9];
    const float* Wk_m  = (const float*)d_in[10]; const float* bk_m = (const float*)d_in[11];
    const float* Wv_m  = (const float*)d_in[12]; const float* bv_m = (const float*)d_in[13];
    const float* Wli   = (const float*)d_in[14]; const float* bli  = (const float*)d_in[15];
    const float* Wlm   = (const float*)d_in[16]; const float* blm  = (const float*)d_in[17];
    float* out = (float*)d_out;

    __nv_bfloat16 *bimg, *bmet, *wqm, *wki, *wvi, *wqi, *wkm, *wvm, *wli, *wlm;
    __nv_bfloat16 *si, *sm, *ci, *cm;
    uint8_t *qm, *ki, *vit, *qi, *km, *vmt, *pi, *pm;
    cudaGetSymbolAddress((void**)&bimg, g_bimg);
    cudaGetSymbolAddress((void**)&bmet, g_bmet);
    cudaGetSymbolAddress((void**)&wqm,  g_wqm);
    cudaGetSymbolAddress((void**)&wki,  g_wki);
    cudaGetSymbolAddress((void**)&wvi,  g_wvi);
    cudaGetSymbolAddress((void**)&wqi,  g_wqi);
    cudaGetSymbolAddress((void**)&wkm,  g_wkm);
    cudaGetSymbolAddress((void**)&wvm,  g_wvm);
    cudaGetSymbolAddress((void**)&wli,  g_wli);
    cudaGetSymbolAddress((void**)&wlm,  g_wlm);
    cudaGetSymbolAddress((void**)&qm,   g_qm);
    cudaGetSymbolAddress((void**)&ki,   g_ki);
    cudaGetSymbolAddress((void**)&vit,  g_vit);
    cudaGetSymbolAddress((void**)&qi,   g_qi);
    cudaGetSymbolAddress((void**)&km,   g_km);
    cudaGetSymbolAddress((void**)&vmt,  g_vmt);
    cudaGetSymbolAddress((void**)&si,   g_si);
    cudaGetSymbolAddress((void**)&sm,   g_sm);
    cudaGetSymbolAddress((void**)&pi,   g_pi);
    cudaGetSymbolAddress((void**)&pm,   g_pm);
    cudaGetSymbolAddress((void**)&ci,   g_ci);
    cudaGetSymbolAddress((void**)&cm,   g_cm);

    cudaFuncSetAttribute(gemm_batch<0>, cudaFuncAttributeMaxDynamicSharedMemorySize, SMEM_DYN);
    cudaFuncSetAttribute(gemm_batch<1>, cudaFuncAttributeMaxDynamicSharedMemorySize, SMEM_DYN);

    // ---- pre-convert all fp32 operands to bf16 (one launch)
    {
        CvtJobs j;
        const int nW = NH * DIM * DIM;
        const int nL = DIM * NH * DIM;
        const int nX = NTOK * DIM;
        j.s[0] = image; j.d[0] = bimg; j.n[0] = nX;
        j.s[1] = meta;  j.d[1] = bmet; j.n[1] = nX;
        j.s[2] = Wq_m;  j.d[2] = wqm;  j.n[2] = nW;
        j.s[3] = Wk_i;  j.d[3] = wki;  j.n[3] = nW;
        j.s[4] = Wv_i;  j.d[4] = wvi;  j.n[4] = nW;
        j.s[5] = Wq_i;  j.d[5] = wqi;  j.n[5] = nW;
        j.s[6] = Wk_m;  j.d[6] = wkm;  j.n[6] = nW;
        j.s[7] = Wv_m;  j.d[7] = wvm;  j.n[7] = nW;
        j.s[8] = Wli;   j.d[8] = wli;  j.n[8] = nL;
        j.s[9] = Wlm;   j.d[9] = wlm;  j.n[9] = nL;
        cvt_bf<<<dim3(1024, 10), 256>>>(j);
    }

    const dim3 blk(256);
    const size_t sW  = (size_t)DIM * DIM;
    const size_t sO  = (size_t)NTOK * DIM;
    const size_t sOT = (size_t)DIM * NTOK;
    const size_t sS  = (size_t)NTOK * NTOK;
    const float scale = 0.04419417382415922f;   // 1/sqrt(512)

    // ---- projections (bf16 in): ONE launch, 48 jobs; Q/K -> fp8, V -> fp8^T
    {
        Jobs jb;
        const __nv_bfloat16* As[6]  = {bmet, bimg, bimg, bimg, bmet, bmet};
        const __nv_bfloat16* Ws[6]  = {wqm,  wki,  wvi,  wqi,  wkm,  wvm};
        uint8_t*             Cs[6]  = {qm,   ki,   vit,  qi,   km,   vmt};
        const float*         Bs[6]  = {bq_m, bk_i, bv_i, bq_i, bk_m, bv_m};
        const int            md[6]  = {3, 3, 4, 3, 3, 4};
        for (int g = 0; g < 6; g++)
            for (int h = 0; h < NH; h++) {
                Job& J = jb.j[g * NH + h];
                J.A = (const char*)As[g];
                J.B = (const char*)(Ws[g] + (size_t)h * sW);
                J.C = (char*)(Cs[g] + (md[g] == 4 ? (size_t)h * sOT : (size_t)h * sO));
                J.bias = Bs[g] + (size_t)h * DIM;
                J.resid = nullptr;
                J.scale = 1.0f;
                J.lda = DIM; J.ldb = DIM;
                J.ldc = (md[g] == 4) ? NTOK : DIM;
                J.ldr = 0; J.outMode = md[g];
            }
        gemm_batch<0><<<dim3(DIM / 128, NTOK / 128, 48), blk, SMEM_DYN>>>(jb, DIM);
    }

    // ---- scores (fp8 in): ONE launch, 16 jobs, bf16 pre-scaled logits out
    {
        Jobs jb;
        for (int p = 0; p < 2; p++)
            for (int h = 0; h < NH; h++) {
                Job& J = jb.j[p * NH + h];
                J.A = (const char*)((p ? qi : qm) + (size_t)h * sO);
                J.B = (const char*)((p ? km : ki) + (size_t)h * sO);
                J.C = (char*)((p ? sm : si) + (size_t)h * sS);
                J.bias = nullptr; J.resid = nullptr;
                J.scale = scale;
                J.lda = DIM; J.ldb = DIM; J.ldc = NTOK; J.ldr = 0; J.outMode = 1;
            }
        gemm_batch<1><<<dim3(NTOK / 128, NTOK / 128, 16), blk, SMEM_DYN>>>(jb, DIM);
    }

    // ---- softmax (both directions): bf16 logits -> fp8 probs*PSCALE
    softmax_bf<<<dim3(NH * NTOK, 2), 256>>>(si, pi, sm, pm);

    // ---- AV (fp8 in): ONE launch, 16 jobs -> concat [2048, 4096] bf16, /PSCALE
    {
        Jobs jb;
        for (int p = 0; p < 2; p++)
            for (int h = 0; h < NH; h++) {
                Job& J = jb.j[p * NH + h];
                J.A = (const char*)((p ? pm : pi) + (size_t)h * sS);
                J.B = (const char*)((p ? vmt : vit) + (size_t)h * sOT);
                J.C = (char*)((p ? cm : ci) + (size_t)h * DIM);
                J.bias = nullptr; J.resid = nullptr;
                J.scale = PSCALE_INV;
                J.lda = NTOK; J.ldb = NTOK; J.ldc = NH * DIM; J.ldr = 0; J.outMode = 1;
            }
        gemm_batch<1><<<dim3(DIM / 128, NTOK / 128, 16), blk, SMEM_DYN>>>(jb, NTOK);
    }

    // ---- final linears (bf16 in): ONE launch, 2 jobs, bias + fp32 residual -> d_out
    {
        Jobs jb;
        jb.j[0] = { (const char*)ci, (const char*)wli, (char*)out,
                    bli, image, 1.0f, NH * DIM, NH * DIM, 2 * DIM, DIM, 0 };
        jb.j[1] = { (const char*)cm, (const char*)wlm, (char*)(out + DIM),
                    blm, meta,  1.0f, NH * DIM, NH * DIM, 2 * DIM, DIM, 0 };
        gemm_batch<0><<<dim3(DIM / 128, NTOK / 128, 2), blk, SMEM_DYN>>>(jb, NH * DIM);
    }
}

// round 16
// speedup vs baseline: 1.0560x; 1.0123x over previous
#include <cuda_runtime.h>
#include <cuda_bf16.h>
#include <cstdint>

static constexpr int NTOK = 2048;
static constexpr int DIM  = 512;
static constexpr int NH   = 8;

// ---------------- scratch (allocation-free: __device__ globals) ----------------
__device__ __align__(128) __nv_bfloat16 g_bimg[(size_t)NTOK * DIM];
__device__ __align__(128) __nv_bfloat16 g_bmet[(size_t)NTOK * DIM];
__device__ __align__(128) __nv_bfloat16 g_wqm [(size_t)NH * DIM * DIM];
__device__ __align__(128) __nv_bfloat16 g_wki [(size_t)NH * DIM * DIM];
__device__ __align__(128) __nv_bfloat16 g_wvi [(size_t)NH * DIM * DIM];
__device__ __align__(128) __nv_bfloat16 g_wqi [(size_t)NH * DIM * DIM];
__device__ __align__(128) __nv_bfloat16 g_wkm [(size_t)NH * DIM * DIM];
__device__ __align__(128) __nv_bfloat16 g_wvm [(size_t)NH * DIM * DIM];
__device__ __align__(128) __nv_bfloat16 g_wli [(size_t)DIM * NH * DIM];
__device__ __align__(128) __nv_bfloat16 g_wlm [(size_t)DIM * NH * DIM];
__device__ __align__(128) uint8_t       g_qm  [(size_t)NH * NTOK * DIM];      // Q fp8
__device__ __align__(128) uint8_t       g_ki  [(size_t)NH * NTOK * DIM];      // K fp8
__device__ __align__(128) uint8_t       g_vit [(size_t)NH * DIM * NTOK];      // V_i^T fp8
__device__ __align__(128) uint8_t       g_qi  [(size_t)NH * NTOK * DIM];
__device__ __align__(128) uint8_t       g_km  [(size_t)NH * NTOK * DIM];
__device__ __align__(128) uint8_t       g_vmt [(size_t)NH * DIM * NTOK];
__device__ __align__(128) uint8_t       g_pi  [(size_t)NH * NTOK * NTOK];     // exp(logit) fp8
__device__ __align__(128) uint8_t       g_pm  [(size_t)NH * NTOK * NTOK];
__device__ __align__(128) float         g_rs  [(size_t)2 * NH * NTOK];        // row sums
__device__ __align__(128) __nv_bfloat16 g_ci  [(size_t)NTOK * NH * DIM];
__device__ __align__(128) __nv_bfloat16 g_cm  [(size_t)NTOK * NH * DIM];

#define DEVINL __device__ __forceinline__

DEVINL uint32_t s2u(const void* p) { return (uint32_t)__cvta_generic_to_shared(p); }

DEVINL void ldsm4(uint32_t* r, uint32_t a) {
    asm volatile("ldmatrix.sync.aligned.m8n8.x4.shared.b16 {%0,%1,%2,%3}, [%4];"
        : "=r"(r[0]), "=r"(r[1]), "=r"(r[2]), "=r"(r[3]) : "r"(a));
}
DEVINL void mma16(float* c, const uint32_t* a, uint32_t b0, uint32_t b1) {
    asm volatile("mma.sync.aligned.m16n8k16.row.col.f32.bf16.bf16.f32 "
        "{%0,%1,%2,%3},{%4,%5,%6,%7},{%8,%9},{%0,%1,%2,%3};"
        : "+f"(c[0]), "+f"(c[1]), "+f"(c[2]), "+f"(c[3])
        : "r"(a[0]), "r"(a[1]), "r"(a[2]), "r"(a[3]), "r"(b0), "r"(b1));
}
DEVINL void mma32f8(float* c, const uint32_t* a, uint32_t b0, uint32_t b1) {
    asm volatile("mma.sync.aligned.m16n8k32.row.col.f32.e4m3.e4m3.f32 "
        "{%0,%1,%2,%3},{%4,%5,%6,%7},{%8,%9},{%0,%1,%2,%3};"
        : "+f"(c[0]), "+f"(c[1]), "+f"(c[2]), "+f"(c[3])
        : "r"(a[0]), "r"(a[1]), "r"(a[2]), "r"(a[3]), "r"(b0), "r"(b1));
}
DEVINL uint32_t pk2(float lo, float hi) {
    __nv_bfloat162 t = __floats2bfloat162_rn(lo, hi);
    return *reinterpret_cast<uint32_t*>(&t);
}
DEVINL uint32_t pk4f8(float v0, float v1, float v2, float v3) {
    uint16_t lo, hi;
    asm("cvt.rn.satfinite.e4m3x2.f32 %0, %1, %2;" : "=h"(lo) : "f"(v1), "f"(v0));
    asm("cvt.rn.satfinite.e4m3x2.f32 %0, %1, %2;" : "=h"(hi) : "f"(v3), "f"(v2));
    return (uint32_t)lo | ((uint32_t)hi << 16);
}
DEVINL void cp16(uint32_t dst, const void* src) {
    asm volatile("cp.async.cg.shared.global [%0], [%1], 16;" :: "r"(dst), "l"(src));
}
#define CP_COMMIT() asm volatile("cp.async.commit_group;")
#define CP_WAIT(n)  asm volatile("cp.async.wait_group %0;" :: "n"(n))

static constexpr int RPB  = 80;   // smem tile row pitch bytes: 64 data + 16 pad
static constexpr int SP   = 132;  // epilogue stage pitch (floats) — mult of 4 (R5 lesson)
static constexpr int NS   = 4;    // cp.async pipeline stages (R13 scheme)
static constexpr int TILE_B  = 128 * RPB;
static constexpr int STAGE_B = 2 * TILE_B;
static constexpr int SMEM_DYN = NS * STAGE_B;        // 81920 B

// --------------- per-z job descriptor (all pointers pre-offset on host) --------
// outMode: 0 fp32(+bias+resid), 1 bf16, 3 fp8, 4 fp8 transposed,
//          5 fp8 exp(acc*scale) + atomic rowsum,  6 bf16 with v /= rowsum[m]
struct Job {
    const char* A;
    const char* B;
    char*       C;
    const float* bias;
    const float* resid;
    float*       rowsum;               // mode 5: write (atomic); mode 6: read
    float scale;
    int lda, ldb, ldc, ldr, outMode;   // lda/ldb/ldc in ELEMENTS of their dtype
};
static constexpr int MAXJ = 48;
struct Jobs { Job j[MAXJ]; };

// ---------------------------------------------------------------------------
// mma GEMM (NT), batched by z over a job table.  (R13 pipeline — converged.)
// F8=0: bf16 operands, K-chunk 32 elems; F8=1: e4m3 operands, K-chunk 64 elems.
// CTA 128x128, 256 thr, warp tile 64x32, 4-stage cp.async, wait(NS-2)/chunk.
// ---------------------------------------------------------------------------
template <int F8>
__global__ __launch_bounds__(256, 2) void gemm_batch(Jobs jobs, int K)
{
    extern __shared__ __align__(128) char dsm[];
    const uint32_t sbase = s2u(dsm);
    const Job J = jobs.j[blockIdx.z];
    const int esz = F8 ? 1 : 2;

    const int tid  = threadIdx.x;
    const int warp = tid >> 5, lane = tid & 31;
    const int wm = warp & 1, wn = warp >> 1;
    const int gid = lane >> 2, tig = lane & 3;
    const int m0 = blockIdx.y * 128, n0 = blockIdx.x * 128;

    const int frow = tid & 127;
    const int fup  = (tid >> 7) * 2;
    const char* Ap = J.A + (size_t)(m0 + frow) * J.lda * esz + fup * 16;
    const char* Bp = J.B + (size_t)(n0 + frow) * J.ldb * esz + fup * 16;
    const uint32_t sa_t = sbase + frow * RPB + fup * 16;
    const uint32_t sb_t = sa_t + TILE_B;

    const int NC = K / (F8 ? 64 : 32);

    auto issue = [&](int c) {
        const uint32_t so = (uint32_t)((c & (NS - 1)) * STAGE_B);
        const char* ga = Ap + (size_t)c * 64;
        const char* gb = Bp + (size_t)c * 64;
        cp16(sa_t + so,      ga);
        cp16(sa_t + so + 16, ga + 16);
        cp16(sb_t + so,      gb);
        cp16(sb_t + so + 16, gb + 16);
    };

    float acc[4][4][4];
#pragma unroll
    for (int i = 0; i < 4; i++)
#pragma unroll
        for (int j = 0; j < 4; j++)
#pragma unroll
            for (int r = 0; r < 4; r++) acc[i][j][r] = 0.0f;

    const int lrow8  = (lane & 7) + ((lane >> 3) & 1) * 8;
    const int lchunk = (lane >> 4) * 16;
    uint32_t aoff[4], boff[2];
#pragma unroll
    for (int mt = 0; mt < 4; mt++) aoff[mt] = (uint32_t)((wm * 64 + mt * 16 + lrow8) * RPB + lchunk);
#pragma unroll
    for (int np = 0; np < 2; np++) boff[np] = (uint32_t)((wn * 32 + np * 16 + lrow8) * RPB + lchunk);

#pragma unroll
    for (int c = 0; c < NS - 1; c++) {
        if (c < NC) issue(c);
        CP_COMMIT();
    }

    for (int c = 0; c < NC; c++) {
        CP_WAIT(NS - 2);
        __syncthreads();
        if (c + NS - 1 < NC) issue(c + NS - 1);
        CP_COMMIT();

        const uint32_t so = (uint32_t)((c & (NS - 1)) * STAGE_B);
        const uint32_t ab = sbase + so;
        const uint32_t bb = ab + TILE_B;
#pragma unroll
        for (int ks = 0; ks < 2; ks++) {
            uint32_t a[4][4], b[2][4];
#pragma unroll
            for (int mt = 0; mt < 4; mt++) ldsm4(a[mt], ab + aoff[mt] + ks * 32);
#pragma unroll
            for (int np = 0; np < 2; np++) ldsm4(b[np], bb + boff[np] + ks * 32);
#pragma unroll
            for (int mt = 0; mt < 4; mt++)
#pragma unroll
                for (int np = 0; np < 2; np++) {
                    if (F8) {
                        mma32f8(acc[mt][2 * np],     a[mt], b[np][0], b[np][2]);
                        mma32f8(acc[mt][2 * np + 1], a[mt], b[np][1], b[np][3]);
                    } else {
                        mma16(acc[mt][2 * np],     a[mt], b[np][0], b[np][2]);
                        mma16(acc[mt][2 * np + 1], a[mt], b[np][1], b[np][3]);
                    }
                }
        }
    }
    CP_WAIT(0);
    __syncthreads();

    // -------- epilogue: stage 64 m-rows at a time through smem --------
    float* stage = (float*)dsm;
    const float sc = J.scale;
    for (int p = 0; p < 2; p++) {
        if (wm == p) {
#pragma unroll
            for (int mt = 0; mt < 4; mt++) {
                const int lr = mt * 16 + gid;
#pragma unroll
                for (int nt = 0; nt < 4; nt++) {
                    const int col = wn * 32 + nt * 8 + 2 * tig;
                    *(float2*)&stage[lr * SP + col]       = make_float2(acc[mt][nt][0], acc[mt][nt][1]);
                    *(float2*)&stage[(lr + 8) * SP + col] = make_float2(acc[mt][nt][2], acc[mt][nt][3]);
                }
            }
        }
        __syncthreads();

        if (J.outMode == 0) {
            float* C = (float*)J.C;
#pragma unroll
            for (int i = 0; i < 8; i++) {
                const int idx = tid + i * 256;
                const int row = idx >> 5;
                const int c4  = (idx & 31) * 4;
                float4 v = *(float4*)&stage[row * SP + c4];
                v.x *= sc; v.y *= sc; v.z *= sc; v.w *= sc;
                const int n = n0 + c4;
                if (J.bias) { v.x += J.bias[n]; v.y += J.bias[n + 1]; v.z += J.bias[n + 2]; v.w += J.bias[n + 3]; }
                const int m = m0 + p * 64 + row;
                if (J.resid) {
                    float4 rr = *(const float4*)(J.resid + (size_t)m * J.ldr + n);
                    v.x += rr.x; v.y += rr.y; v.z += rr.z; v.w += rr.w;
                }
                *(float4*)(C + (size_t)m * J.ldc + n) = v;
            }
        } else if (J.outMode == 1) {
            __nv_bfloat16* C = (__nv_bfloat16*)J.C;
#pragma unroll
            for (int i = 0; i < 8; i++) {
                const int idx = tid + i * 256;
                const int row = idx >> 5;
                const int c4  = (idx & 31) * 4;
                float4 v = *(float4*)&stage[row * SP + c4];
                v.x *= sc; v.y *= sc; v.z *= sc; v.w *= sc;
                const int n = n0 + c4;
                if (J.bias) { v.x += J.bias[n]; v.y += J.bias[n + 1]; v.z += J.bias[n + 2]; v.w += J.bias[n + 3]; }
                uint2 o = make_uint2(pk2(v.x, v.y), pk2(v.z, v.w));
                *(uint2*)(C + (size_t)(m0 + p * 64 + row) * J.ldc + n) = o;
            }
        } else if (J.outMode == 3) {
            uint8_t* C = (uint8_t*)J.C;
#pragma unroll
            for (int i = 0; i < 8; i++) {
                const int idx = tid + i * 256;
                const int row = idx >> 5;
                const int c4  = (idx & 31) * 4;
                float4 v = *(float4*)&stage[row * SP + c4];
                v.x *= sc; v.y *= sc; v.z *= sc; v.w *= sc;
                const int n = n0 + c4;
                if (J.bias) { v.x += J.bias[n]; v.y += J.bias[n + 1]; v.z += J.bias[n + 2]; v.w += J.bias[n + 3]; }
                *(uint32_t*)(C + (size_t)(m0 + p * 64 + row) * J.ldc + n) = pk4f8(v.x, v.y, v.z, v.w);
            }
        } else if (J.outMode == 4) {
            uint8_t* C = (uint8_t*)J.C;
#pragma unroll
            for (int i = 0; i < 8; i++) {
                const int idx = tid + i * 256;
                const int mq  = (idx & 15) * 4;
                const int col = idx >> 4;
                const float bv = J.bias ? J.bias[n0 + col] : 0.0f;
                float f0 = stage[(mq + 0) * SP + col] * sc + bv;
                float f1 = stage[(mq + 1) * SP + col] * sc + bv;
                float f2 = stage[(mq + 2) * SP + col] * sc + bv;
                float f3 = stage[(mq + 3) * SP + col] * sc + bv;
                *(uint32_t*)(C + (size_t)(n0 + col) * J.ldc + m0 + p * 64 + mq) = pk4f8(f0, f1, f2, f3);
            }
        } else if (J.outMode == 5) {
            // fp8 exp(acc*scale) + per-row sum via warp-reduce + one atomicAdd.
            // For iteration i, ALL lanes of warp w hold row = 8*i + w (lane*4 = col).
            uint8_t* C = (uint8_t*)J.C;
#pragma unroll
            for (int i = 0; i < 8; i++) {
                const int idx = tid + i * 256;
                const int row = idx >> 5;            // == 8*i + warp
                const int c4  = (idx & 31) * 4;
                float4 v = *(float4*)&stage[row * SP + c4];
                v.x = __expf(v.x * sc); v.y = __expf(v.y * sc);
                v.z = __expf(v.z * sc); v.w = __expf(v.w * sc);
                *(uint32_t*)(C + (size_t)(m0 + p * 64 + row) * J.ldc + n0 + c4) =
                    pk4f8(v.x, v.y, v.z, v.w);
                float rs = (v.x + v.y) + (v.z + v.w);
#pragma unroll
                for (int o = 16; o; o >>= 1) rs += __shfl_xor_sync(0xffffffffu, rs, o);
                if (lane == 0) atomicAdd(J.rowsum + m0 + p * 64 + row, rs);
            }
        } else {
            // mode 6: bf16 out, divide row m by rowsum[m] (deferred softmax norm)
            __nv_bfloat16* C = (__nv_bfloat16*)J.C;
#pragma unroll
            for (int i = 0; i < 8; i++) {
                const int idx = tid + i * 256;
                const int row = idx >> 5;
                const int c4  = (idx & 31) * 4;
                float4 v = *(float4*)&stage[row * SP + c4];
                const float r = 1.0f / J.rowsum[m0 + p * 64 + row];
                v.x *= r; v.y *= r; v.z *= r; v.w *= r;
                uint2 o = make_uint2(pk2(v.x, v.y), pk2(v.z, v.w));
                *(uint2*)(C + (size_t)(m0 + p * 64 + row) * J.ldc + n0 + c4) = o;
            }
        }
        __syncthreads();
    }
}

// ---------------------------------------------------------------------------
// fp32 -> bf16 bulk convert, 10 tensors in one launch (grid.y = tensor idx)
// ---------------------------------------------------------------------------
struct CvtJobs { const float* s[10]; __nv_bfloat16* d[10]; int n[10]; };

__global__ __launch_bounds__(256) void cvt_bf(CvtJobs j)
{
    const int t = blockIdx.y;
    const float* src = j.s[t];
    __nv_bfloat16* dst = j.d[t];
    const int n = j.n[t];
    const int stride = gridDim.x * blockDim.x * 4;
    for (int i = (blockIdx.x * blockDim.x + threadIdx.x) * 4; i < n; i += stride) {
        float4 v = *(const float4*)(src + i);
        uint2 o = make_uint2(pk2(v.x, v.y), pk2(v.z, v.w));
        *(uint2*)(dst + i) = o;
    }
}

// ---------------------------------------------------------------------------
extern "C" void kernel_launch(void* const* d_in, const int* in_sizes, int n_in,
                              void* d_out, int out_size)
{
    (void)in_sizes; (void)n_in; (void)out_size;

    const float* image = (const float*)d_in[0];
    const float* meta  = (const float*)d_in[1];
    const float* Wq_m  = (const float*)d_in[2];  const float* bq_m = (const float*)d_in[3];
    const float* Wk_i  = (const float*)d_in[4];  const float* bk_i = (const float*)d_in[5];
    const float* Wv_i  = (const float*)d_in[6];  const float* bv_i = (const float*)d_in[7];
    const float* Wq_i  = (const float*)d_in[8];  const float* bq_i = (const float*)d_in[9];
    const float* Wk_m  = (const float*)d_in[10]; const float* bk_m = (const float*)d_in[11];
    const float* Wv_m  = (const float*)d_in[12]; const float* bv_m = (const float*)d_in[13];
    const float* Wli   = (const float*)d_in[14]; const float* bli  = (const float*)d_in[15];
    const float* Wlm   = (const float*)d_in[16]; const float* blm  = (const float*)d_in[17];
    float* out = (float*)d_out;

    __nv_bfloat16 *bimg, *bmet, *wqm, *wki, *wvi, *wqi, *wkm, *wvm, *wli, *wlm, *ci, *cm;
    uint8_t *qm, *ki, *vit, *qi, *km, *vmt, *pi, *pm;
    float *rs;
    cudaGetSymbolAddress((void**)&bimg, g_bimg);
    cudaGetSymbolAddress((void**)&bmet, g_bmet);
    cudaGetSymbolAddress((void**)&wqm,  g_wqm);
    cudaGetSymbolAddress((void**)&wki,  g_wki);
    cudaGetSymbolAddress((void**)&wvi,  g_wvi);
    cudaGetSymbolAddress((void**)&wqi,  g_wqi);
    cudaGetSymbolAddress((void**)&wkm,  g_wkm);
    cudaGetSymbolAddress((void**)&wvm,  g_wvm);
    cudaGetSymbolAddress((void**)&wli,  g_wli);
    cudaGetSymbolAddress((void**)&wlm,  g_wlm);
    cudaGetSymbolAddress((void**)&qm,   g_qm);
    cudaGetSymbolAddress((void**)&ki,   g_ki);
    cudaGetSymbolAddress((void**)&vit,  g_vit);
    cudaGetSymbolAddress((void**)&qi,   g_qi);
    cudaGetSymbolAddress((void**)&km,   g_km);
    cudaGetSymbolAddress((void**)&vmt,  g_vmt);
    cudaGetSymbolAddress((void**)&pi,   g_pi);
    cudaGetSymbolAddress((void**)&pm,   g_pm);
    cudaGetSymbolAddress((void**)&rs,   g_rs);
    cudaGetSymbolAddress((void**)&ci,   g_ci);
    cudaGetSymbolAddress((void**)&cm,   g_cm);

    cudaFuncSetAttribute(gemm_batch<0>, cudaFuncAttributeMaxDynamicSharedMemorySize, SMEM_DYN);
    cudaFuncSetAttribute(gemm_batch<1>, cudaFuncAttributeMaxDynamicSharedMemorySize, SMEM_DYN);

    // ---- zero rowsums (graph-capturable memset node) + convert inputs to bf16
    cudaMemsetAsync(rs, 0, (size_t)2 * NH * NTOK * sizeof(float));
    {
        CvtJobs j;
        const int nW = NH * DIM * DIM;
        const int nL = DIM * NH * DIM;
        const int nX = NTOK * DIM;
        j.s[0] = image; j.d[0] = bimg; j.n[0] = nX;
        j.s[1] = meta;  j.d[1] = bmet; j.n[1] = nX;
        j.s[2] = Wq_m;  j.d[2] = wqm;  j.n[2] = nW;
        j.s[3] = Wk_i;  j.d[3] = wki;  j.n[3] = nW;
        j.s[4] = Wv_i;  j.d[4] = wvi;  j.n[4] = nW;
        j.s[5] = Wq_i;  j.d[5] = wqi;  j.n[5] = nW;
        j.s[6] = Wk_m;  j.d[6] = wkm;  j.n[6] = nW;
        j.s[7] = Wv_m;  j.d[7] = wvm;  j.n[7] = nW;
        j.s[8] = Wli;   j.d[8] = wli;  j.n[8] = nL;
        j.s[9] = Wlm;   j.d[9] = wlm;  j.n[9] = nL;
        cvt_bf<<<dim3(1024, 10), 256>>>(j);
    }

    const dim3 blk(256);
    const size_t sW  = (size_t)DIM * DIM;
    const size_t sO  = (size_t)NTOK * DIM;
    const size_t sOT = (size_t)DIM * NTOK;
    const size_t sS  = (size_t)NTOK * NTOK;
    const float scale = 0.04419417382415922f;   // 1/sqrt(512)

    // ---- projections (bf16 in): ONE launch, 48 jobs; Q/K -> fp8, V -> fp8^T
    {
        Jobs jb;
        const __nv_bfloat16* As[6]  = {bmet, bimg, bimg, bimg, bmet, bmet};
        const __nv_bfloat16* Ws[6]  = {wqm,  wki,  wvi,  wqi,  wkm,  wvm};
        uint8_t*             Cs[6]  = {qm,   ki,   vit,  qi,   km,   vmt};
        const float*         Bs[6]  = {bq_m, bk_i, bv_i, bq_i, bk_m, bv_m};
        const int            md[6]  = {3, 3, 4, 3, 3, 4};
        for (int g = 0; g < 6; g++)
            for (int h = 0; h < NH; h++) {
                Job& J = jb.j[g * NH + h];
                J.A = (const char*)As[g];
                J.B = (const char*)(Ws[g] + (size_t)h * sW);
                J.C = (char*)(Cs[g] + (md[g] == 4 ? (size_t)h * sOT : (size_t)h * sO));
                J.bias = Bs[g] + (size_t)h * DIM;
                J.resid = nullptr; J.rowsum = nullptr;
                J.scale = 1.0f;
                J.lda = DIM; J.ldb = DIM;
                J.ldc = (md[g] == 4) ? NTOK : DIM;
                J.ldr = 0; J.outMode = md[g];
            }
        gemm_batch<0><<<dim3(DIM / 128, NTOK / 128, 48), blk, SMEM_DYN>>>(jb, DIM);
    }

    // ---- scores (fp8 in): ONE launch, 16 jobs — fp8 exp(logit) out + rowsums
    {
        Jobs jb;
        for (int p = 0; p < 2; p++)
            for (int h = 0; h < NH; h++) {
                Job& J = jb.j[p * NH + h];
                J.A = (const char*)((p ? qi : qm) + (size_t)h * sO);
                J.B = (const char*)((p ? km : ki) + (size_t)h * sO);
                J.C = (char*)((p ? pm : pi) + (size_t)h * sS);
                J.bias = nullptr; J.resid = nullptr;
                J.rowsum = rs + (size_t)(p * NH + h) * NTOK;
                J.scale = scale;
                J.lda = DIM; J.ldb = DIM; J.ldc = NTOK; J.ldr = 0; J.outMode = 5;
            }
        gemm_batch<1><<<dim3(NTOK / 128, NTOK / 128, 16), blk, SMEM_DYN>>>(jb, DIM);
    }

    // ---- AV (fp8 in): ONE launch, 16 jobs -> concat bf16, row-normalized
    {
        Jobs jb;
        for (int p = 0; p < 2; p++)
            for (int h = 0; h < NH; h++) {
                Job& J = jb.j[p * NH + h];
                J.A = (const char*)((p ? pm : pi) + (size_t)h * sS);
                J.B = (const char*)((p ? vmt : vit) + (size_t)h * sOT);
                J.C = (char*)((p ? cm : ci) + (size_t)h * DIM);
                J.bias = nullptr; J.resid = nullptr;
                J.rowsum = rs + (size_t)(p * NH + h) * NTOK;
                J.scale = 1.0f;
                J.lda = NTOK; J.ldb = NTOK; J.ldc = NH * DIM; J.ldr = 0; J.outMode = 6;
            }
        gemm_batch<1><<<dim3(DIM / 128, NTOK / 128, 16), blk, SMEM_DYN>>>(jb, NTOK);
    }

    // ---- final linears (bf16 in): ONE launch, 2 jobs, bias + fp32 residual -> d_out
    {
        Jobs jb;
        jb.j[0] = { (const char*)ci, (const char*)wli, (char*)out,
                    bli, image, nullptr, 1.0f, NH * DIM, NH * DIM, 2 * DIM, DIM, 0 };
        jb.j[1] = { (const char*)cm, (const char*)wlm, (char*)(out + DIM),
                    blm, meta,  nullptr, 1.0f, NH * DIM, NH * DIM, 2 * DIM, DIM, 0 };
        gemm_batch<0><<<dim3(DIM / 128, NTOK / 128, 2), blk, SMEM_DYN>>>(jb, NH * DIM);
    }
}

// round 17
// speedup vs baseline: 1.1284x; 1.0686x over previous
#include <cuda_runtime.h>
#include <cuda_bf16.h>
#include <cstdint>

static constexpr int NTOK = 2048;
static constexpr int DIM  = 512;
static constexpr int NH   = 8;

// ---------------- scratch (allocation-free: __device__ globals) ----------------
__device__ __align__(128) uint8_t       g_bimg[(size_t)NTOK * DIM];           // image fp8
__device__ __align__(128) uint8_t       g_bmet[(size_t)NTOK * DIM];           // meta  fp8
__device__ __align__(128) uint8_t       g_wqm [(size_t)NH * DIM * DIM];       // proj weights fp8
__device__ __align__(128) uint8_t       g_wki [(size_t)NH * DIM * DIM];
__device__ __align__(128) uint8_t       g_wvi [(size_t)NH * DIM * DIM];
__device__ __align__(128) uint8_t       g_wqi [(size_t)NH * DIM * DIM];
__device__ __align__(128) uint8_t       g_wkm [(size_t)NH * DIM * DIM];
__device__ __align__(128) uint8_t       g_wvm [(size_t)NH * DIM * DIM];
__device__ __align__(128) __nv_bfloat16 g_wli [(size_t)DIM * NH * DIM];       // final W bf16
__device__ __align__(128) __nv_bfloat16 g_wlm [(size_t)DIM * NH * DIM];
__device__ __align__(128) uint8_t       g_qm  [(size_t)NH * NTOK * DIM];      // Q fp8
__device__ __align__(128) uint8_t       g_ki  [(size_t)NH * NTOK * DIM];
__device__ __align__(128) uint8_t       g_vit [(size_t)NH * DIM * NTOK];      // V^T fp8
__device__ __align__(128) uint8_t       g_qi  [(size_t)NH * NTOK * DIM];
__device__ __align__(128) uint8_t       g_km  [(size_t)NH * NTOK * DIM];
__device__ __align__(128) uint8_t       g_vmt [(size_t)NH * DIM * NTOK];
__device__ __align__(128) uint8_t       g_pi  [(size_t)NH * NTOK * NTOK];     // exp(logit) fp8
__device__ __align__(128) uint8_t       g_pm  [(size_t)NH * NTOK * NTOK];
__device__ __align__(128) float         g_rs  [(size_t)2 * NH * NTOK];        // row sums
__device__ __align__(128) __nv_bfloat16 g_ci  [(size_t)NTOK * NH * DIM];
__device__ __align__(128) __nv_bfloat16 g_cm  [(size_t)NTOK * NH * DIM];

#define DEVINL __device__ __forceinline__

DEVINL uint32_t s2u(const void* p) { return (uint32_t)__cvta_generic_to_shared(p); }

DEVINL void ldsm4(uint32_t* r, uint32_t a) {
    asm volatile("ldmatrix.sync.aligned.m8n8.x4.shared.b16 {%0,%1,%2,%3}, [%4];"
        : "=r"(r[0]), "=r"(r[1]), "=r"(r[2]), "=r"(r[3]) : "r"(a));
}
DEVINL void mma16(float* c, const uint32_t* a, uint32_t b0, uint32_t b1) {
    asm volatile("mma.sync.aligned.m16n8k16.row.col.f32.bf16.bf16.f32 "
        "{%0,%1,%2,%3},{%4,%5,%6,%7},{%8,%9},{%0,%1,%2,%3};"
        : "+f"(c[0]), "+f"(c[1]), "+f"(c[2]), "+f"(c[3])
        : "r"(a[0]), "r"(a[1]), "r"(a[2]), "r"(a[3]), "r"(b0), "r"(b1));
}
DEVINL void mma32f8(float* c, const uint32_t* a, uint32_t b0, uint32_t b1) {
    asm volatile("mma.sync.aligned.m16n8k32.row.col.f32.e4m3.e4m3.f32 "
        "{%0,%1,%2,%3},{%4,%5,%6,%7},{%8,%9},{%0,%1,%2,%3};"
        : "+f"(c[0]), "+f"(c[1]), "+f"(c[2]), "+f"(c[3])
        : "r"(a[0]), "r"(a[1]), "r"(a[2]), "r"(a[3]), "r"(b0), "r"(b1));
}
DEVINL uint32_t pk2(float lo, float hi) {
    __nv_bfloat162 t = __floats2bfloat162_rn(lo, hi);
    return *reinterpret_cast<uint32_t*>(&t);
}
DEVINL uint32_t pk4f8(float v0, float v1, float v2, float v3) {
    uint16_t lo, hi;
    asm("cvt.rn.satfinite.e4m3x2.f32 %0, %1, %2;" : "=h"(lo) : "f"(v1), "f"(v0));
    asm("cvt.rn.satfinite.e4m3x2.f32 %0, %1, %2;" : "=h"(hi) : "f"(v3), "f"(v2));
    return (uint32_t)lo | ((uint32_t)hi << 16);
}
DEVINL void cp16(uint32_t dst, const void* src) {
    asm volatile("cp.async.cg.shared.global [%0], [%1], 16;" :: "r"(dst), "l"(src));
}
#define CP_COMMIT() asm volatile("cp.async.commit_group;")
#define CP_WAIT(n)  asm volatile("cp.async.wait_group %0;" :: "n"(n))

static constexpr int RPB  = 80;   // smem tile row pitch bytes: 64 data + 16 pad
static constexpr int SP   = 132;  // epilogue stage pitch (floats) — mult of 4 (R5 lesson)
static constexpr int NS   = 4;    // cp.async pipeline stages (R13 scheme)
static constexpr int TILE_B  = 128 * RPB;
static constexpr int STAGE_B = 2 * TILE_B;
static constexpr int SMEM_DYN = NS * STAGE_B;        // 81920 B

// --------------- per-z job descriptor (all pointers pre-offset on host) --------
// outMode: 0 fp32(+bias+resid), 1 bf16, 3 fp8, 4 fp8 transposed,
//          5 fp8 exp(acc*scale) + atomic rowsum,  6 bf16 with v /= rowsum[m]
struct Job {
    const char* A;
    const char* B;
    char*       C;
    const float* bias;
    const float* resid;
    float*       rowsum;
    float scale;
    int lda, ldb, ldc, ldr, outMode;   // lda/ldb/ldc in ELEMENTS of their dtype
};
static constexpr int MAXJ = 48;
struct Jobs { Job j[MAXJ]; };

// ---------------------------------------------------------------------------
// mma GEMM (NT), batched by z over a job table.  (R13 pipeline — converged.)
// F8=0: bf16 operands, K-chunk 32 elems; F8=1: e4m3 operands, K-chunk 64 elems.
// CTA 128x128, 256 thr, warp tile 64x32, 4-stage cp.async, wait(NS-2)/chunk.
// ---------------------------------------------------------------------------
template <int F8>
__global__ __launch_bounds__(256, 2) void gemm_batch(Jobs jobs, int K)
{
    extern __shared__ __align__(128) char dsm[];
    const uint32_t sbase = s2u(dsm);
    const Job J = jobs.j[blockIdx.z];
    const int esz = F8 ? 1 : 2;

    const int tid  = threadIdx.x;
    const int warp = tid >> 5, lane = tid & 31;
    const int wm = warp & 1, wn = warp >> 1;
    const int gid = lane >> 2, tig = lane & 3;
    const int m0 = blockIdx.y * 128, n0 = blockIdx.x * 128;

    const int frow = tid & 127;
    const int fup  = (tid >> 7) * 2;
    const char* Ap = J.A + (size_t)(m0 + frow) * J.lda * esz + fup * 16;
    const char* Bp = J.B + (size_t)(n0 + frow) * J.ldb * esz + fup * 16;
    const uint32_t sa_t = sbase + frow * RPB + fup * 16;
    const uint32_t sb_t = sa_t + TILE_B;

    const int NC = K / (F8 ? 64 : 32);

    auto issue = [&](int c) {
        const uint32_t so = (uint32_t)((c & (NS - 1)) * STAGE_B);
        const char* ga = Ap + (size_t)c * 64;
        const char* gb = Bp + (size_t)c * 64;
        cp16(sa_t + so,      ga);
        cp16(sa_t + so + 16, ga + 16);
        cp16(sb_t + so,      gb);
        cp16(sb_t + so + 16, gb + 16);
    };

    float acc[4][4][4];
#pragma unroll
    for (int i = 0; i < 4; i++)
#pragma unroll
        for (int j = 0; j < 4; j++)
#pragma unroll
            for (int r = 0; r < 4; r++) acc[i][j][r] = 0.0f;

    const int lrow8  = (lane & 7) + ((lane >> 3) & 1) * 8;
    const int lchunk = (lane >> 4) * 16;
    uint32_t aoff[4], boff[2];
#pragma unroll
    for (int mt = 0; mt < 4; mt++) aoff[mt] = (uint32_t)((wm * 64 + mt * 16 + lrow8) * RPB + lchunk);
#pragma unroll
    for (int np = 0; np < 2; np++) boff[np] = (uint32_t)((wn * 32 + np * 16 + lrow8) * RPB + lchunk);

#pragma unroll
    for (int c = 0; c < NS - 1; c++) {
        if (c < NC) issue(c);
        CP_COMMIT();
    }

    for (int c = 0; c < NC; c++) {
        CP_WAIT(NS - 2);
        __syncthreads();
        if (c + NS - 1 < NC) issue(c + NS - 1);
        CP_COMMIT();

        const uint32_t so = (uint32_t)((c & (NS - 1)) * STAGE_B);
        const uint32_t ab = sbase + so;
        const uint32_t bb = ab + TILE_B;
#pragma unroll
        for (int ks = 0; ks < 2; ks++) {
            uint32_t a[4][4], b[2][4];
#pragma unroll
            for (int mt = 0; mt < 4; mt++) ldsm4(a[mt], ab + aoff[mt] + ks * 32);
#pragma unroll
            for (int np = 0; np < 2; np++) ldsm4(b[np], bb + boff[np] + ks * 32);
#pragma unroll
            for (int mt = 0; mt < 4; mt++)
#pragma unroll
                for (int np = 0; np < 2; np++) {
                    if (F8) {
                        mma32f8(acc[mt][2 * np],     a[mt], b[np][0], b[np][2]);
                        mma32f8(acc[mt][2 * np + 1], a[mt], b[np][1], b[np][3]);
                    } else {
                        mma16(acc[mt][2 * np],     a[mt], b[np][0], b[np][2]);
                        mma16(acc[mt][2 * np + 1], a[mt], b[np][1], b[np][3]);
                    }
                }
        }
    }
    CP_WAIT(0);
    __syncthreads();

    // -------- epilogue: stage 64 m-rows at a time through smem --------
    float* stage = (float*)dsm;
    const float sc = J.scale;
    for (int p = 0; p < 2; p++) {
        if (wm == p) {
#pragma unroll
            for (int mt = 0; mt < 4; mt++) {
                const int lr = mt * 16 + gid;
#pragma unroll
                for (int nt = 0; nt < 4; nt++) {
                    const int col = wn * 32 + nt * 8 + 2 * tig;
                    *(float2*)&stage[lr * SP + col]       = make_float2(acc[mt][nt][0], acc[mt][nt][1]);
                    *(float2*)&stage[(lr + 8) * SP + col] = make_float2(acc[mt][nt][2], acc[mt][nt][3]);
                }
            }
        }
        __syncthreads();

        if (J.outMode == 0) {
            float* C = (float*)J.C;
#pragma unroll
            for (int i = 0; i < 8; i++) {
                const int idx = tid + i * 256;
                const int row = idx >> 5;
                const int c4  = (idx & 31) * 4;
                float4 v = *(float4*)&stage[row * SP + c4];
                v.x *= sc; v.y *= sc; v.z *= sc; v.w *= sc;
                const int n = n0 + c4;
                if (J.bias) { v.x += J.bias[n]; v.y += J.bias[n + 1]; v.z += J.bias[n + 2]; v.w += J.bias[n + 3]; }
                const int m = m0 + p * 64 + row;
                if (J.resid) {
                    float4 rr = *(const float4*)(J.resid + (size_t)m * J.ldr + n);
                    v.x += rr.x; v.y += rr.y; v.z += rr.z; v.w += rr.w;
                }
                *(float4*)(C + (size_t)m * J.ldc + n) = v;
            }
        } else if (J.outMode == 1) {
            __nv_bfloat16* C = (__nv_bfloat16*)J.C;
#pragma unroll
            for (int i = 0; i < 8; i++) {
                const int idx = tid + i * 256;
                const int row = idx >> 5;
                const int c4  = (idx & 31) * 4;
                float4 v = *(float4*)&stage[row * SP + c4];
                v.x *= sc; v.y *= sc; v.z *= sc; v.w *= sc;
                const int n = n0 + c4;
                if (J.bias) { v.x += J.bias[n]; v.y += J.bias[n + 1]; v.z += J.bias[n + 2]; v.w += J.bias[n + 3]; }
                uint2 o = make_uint2(pk2(v.x, v.y), pk2(v.z, v.w));
                *(uint2*)(C + (size_t)(m0 + p * 64 + row) * J.ldc + n) = o;
            }
        } else if (J.outMode == 3) {
            uint8_t* C = (uint8_t*)J.C;
#pragma unroll
            for (int i = 0; i < 8; i++) {
                const int idx = tid + i * 256;
                const int row = idx >> 5;
                const int c4  = (idx & 31) * 4;
                float4 v = *(float4*)&stage[row * SP + c4];
                v.x *= sc; v.y *= sc; v.z *= sc; v.w *= sc;
                const int n = n0 + c4;
                if (J.bias) { v.x += J.bias[n]; v.y += J.bias[n + 1]; v.z += J.bias[n + 2]; v.w += J.bias[n + 3]; }
                *(uint32_t*)(C + (size_t)(m0 + p * 64 + row) * J.ldc + n) = pk4f8(v.x, v.y, v.z, v.w);
            }
        } else if (J.outMode == 4) {
            uint8_t* C = (uint8_t*)J.C;
#pragma unroll
            for (int i = 0; i < 8; i++) {
                const int idx = tid + i * 256;
                const int mq  = (idx & 15) * 4;
                const int col = idx >> 4;
                const float bv = J.bias ? J.bias[n0 + col] : 0.0f;
                float f0 = stage[(mq + 0) * SP + col] * sc + bv;
                float f1 = stage[(mq + 1) * SP + col] * sc + bv;
                float f2 = stage[(mq + 2) * SP + col] * sc + bv;
                float f3 = stage[(mq + 3) * SP + col] * sc + bv;
                *(uint32_t*)(C + (size_t)(n0 + col) * J.ldc + m0 + p * 64 + mq) = pk4f8(f0, f1, f2, f3);
            }
        } else if (J.outMode == 5) {
            // fp8 exp(acc*scale) + per-row sum via warp-reduce + one atomicAdd.
            uint8_t* C = (uint8_t*)J.C;
#pragma unroll
            for (int i = 0; i < 8; i++) {
                const int idx = tid + i * 256;
                const int row = idx >> 5;            // == 8*i + warp
                const int c4  = (idx & 31) * 4;
                float4 v = *(float4*)&stage[row * SP + c4];
                v.x = __expf(v.x * sc); v.y = __expf(v.y * sc);
                v.z = __expf(v.z * sc); v.w = __expf(v.w * sc);
                *(uint32_t*)(C + (size_t)(m0 + p * 64 + row) * J.ldc + n0 + c4) =
                    pk4f8(v.x, v.y, v.z, v.w);
                float rsum = (v.x + v.y) + (v.z + v.w);
#pragma unroll
                for (int o = 16; o; o >>= 1) rsum += __shfl_xor_sync(0xffffffffu, rsum, o);
                if (lane == 0) atomicAdd(J.rowsum + m0 + p * 64 + row, rsum);
            }
        } else {
            // mode 6: bf16 out, divide row m by rowsum[m] (deferred softmax norm)
            __nv_bfloat16* C = (__nv_bfloat16*)J.C;
#pragma unroll
            for (int i = 0; i < 8; i++) {
                const int idx = tid + i * 256;
                const int row = idx >> 5;
                const int c4  = (idx & 31) * 4;
                float4 v = *(float4*)&stage[row * SP + c4];
                const float r = 1.0f / J.rowsum[m0 + p * 64 + row];
                v.x *= r; v.y *= r; v.z *= r; v.w *= r;
                uint2 o = make_uint2(pk2(v.x, v.y), pk2(v.z, v.w));
                *(uint2*)(C + (size_t)(m0 + p * 64 + row) * J.ldc + n0 + c4) = o;
            }
        }
        __syncthreads();
    }
}

// ---------------------------------------------------------------------------
// fp32 -> bf16 or fp8 bulk convert, 10 tensors in one launch
// ---------------------------------------------------------------------------
struct CvtJobs { const float* s[10]; void* d[10]; int n[10]; int f8[10]; };

__global__ __launch_bounds__(256) void cvt_bf(CvtJobs j)
{
    const int t = blockIdx.y;
    const float* src = j.s[t];
    const int n = j.n[t];
    const int isF8 = j.f8[t];
    const int stride = gridDim.x * blockDim.x * 8;
    for (int i = (blockIdx.x * blockDim.x + threadIdx.x) * 8; i < n; i += stride) {
        float4 v0 = *(const float4*)(src + i);
        float4 v1 = *(const float4*)(src + i + 4);
        if (isF8) {
            uint2 o = make_uint2(pk4f8(v0.x, v0.y, v0.z, v0.w),
                                 pk4f8(v1.x, v1.y, v1.z, v1.w));
            *(uint2*)((uint8_t*)j.d[t] + i) = o;
        } else {
            uint4 o = make_uint4(pk2(v0.x, v0.y), pk2(v0.z, v0.w),
                                 pk2(v1.x, v1.y), pk2(v1.z, v1.w));
            *(uint4*)((__nv_bfloat16*)j.d[t] + i) = o;
        }
    }
}

// ---------------------------------------------------------------------------
extern "C" void kernel_launch(void* const* d_in, const int* in_sizes, int n_in,
                              void* d_out, int out_size)
{
    (void)in_sizes; (void)n_in; (void)out_size;

    const float* image = (const float*)d_in[0];
    const float* meta  = (const float*)d_in[1];
    const float* Wq_m  = (const float*)d_in[2];  const float* bq_m = (const float*)d_in[3];
    const float* Wk_i  = (const float*)d_in[4];  const float* bk_i = (const float*)d_in[5];
    const float* Wv_i  = (const float*)d_in[6];  const float* bv_i = (const float*)d_in[7];
    const float* Wq_i  = (const float*)d_in[8];  const float* bq_i = (const float*)d_in[9];
    const float* Wk_m  = (const float*)d_in[10]; const float* bk_m = (const float*)d_in[11];
    const float* Wv_m  = (const float*)d_in[12]; const float* bv_m = (const float*)d_in[13];
    const float* Wli   = (const float*)d_in[14]; const float* bli  = (const float*)d_in[15];
    const float* Wlm   = (const float*)d_in[16]; const float* blm  = (const float*)d_in[17];
    float* out = (float*)d_out;

    uint8_t *bimg, *bmet, *wqm, *wki, *wvi, *wqi, *wkm, *wvm;
    __nv_bfloat16 *wli, *wlm, *ci, *cm;
    uint8_t *qm, *ki, *vit, *qi, *km, *vmt, *pi, *pm;
    float *rs;
    cudaGetSymbolAddress((void**)&bimg, g_bimg);
    cudaGetSymbolAddress((void**)&bmet, g_bmet);
    cudaGetSymbolAddress((void**)&wqm,  g_wqm);
    cudaGetSymbolAddress((void**)&wki,  g_wki);
    cudaGetSymbolAddress((void**)&wvi,  g_wvi);
    cudaGetSymbolAddress((void**)&wqi,  g_wqi);
    cudaGetSymbolAddress((void**)&wkm,  g_wkm);
    cudaGetSymbolAddress((void**)&wvm,  g_wvm);
    cudaGetSymbolAddress((void**)&wli,  g_wli);
    cudaGetSymbolAddress((void**)&wlm,  g_wlm);
    cudaGetSymbolAddress((void**)&qm,   g_qm);
    cudaGetSymbolAddress((void**)&ki,   g_ki);
    cudaGetSymbolAddress((void**)&vit,  g_vit);
    cudaGetSymbolAddress((void**)&qi,   g_qi);
    cudaGetSymbolAddress((void**)&km,   g_km);
    cudaGetSymbolAddress((void**)&vmt,  g_vmt);
    cudaGetSymbolAddress((void**)&pi,   g_pi);
    cudaGetSymbolAddress((void**)&pm,   g_pm);
    cudaGetSymbolAddress((void**)&rs,   g_rs);
    cudaGetSymbolAddress((void**)&ci,   g_ci);
    cudaGetSymbolAddress((void**)&cm,   g_cm);

    cudaFuncSetAttribute(gemm_batch<0>, cudaFuncAttributeMaxDynamicSharedMemorySize, SMEM_DYN);
    cudaFuncSetAttribute(gemm_batch<1>, cudaFuncAttributeMaxDynamicSharedMemorySize, SMEM_DYN);

    // ---- zero rowsums + convert inputs (8 tensors -> fp8, 2 final-W -> bf16)
    cudaMemsetAsync(rs, 0, (size_t)2 * NH * NTOK * sizeof(float));
    {
        CvtJobs j;
        const int nW = NH * DIM * DIM;
        const int nL = DIM * NH * DIM;
        const int nX = NTOK * DIM;
        j.s[0] = image; j.d[0] = bimg; j.n[0] = nX; j.f8[0] = 1;
        j.s[1] = meta;  j.d[1] = bmet; j.n[1] = nX; j.f8[1] = 1;
        j.s[2] = Wq_m;  j.d[2] = wqm;  j.n[2] = nW; j.f8[2] = 1;
        j.s[3] = Wk_i;  j.d[3] = wki;  j.n[3] = nW; j.f8[3] = 1;
        j.s[4] = Wv_i;  j.d[4] = wvi;  j.n[4] = nW; j.f8[4] = 1;
        j.s[5] = Wq_i;  j.d[5] = wqi;  j.n[5] = nW; j.f8[5] = 1;
        j.s[6] = Wk_m;  j.d[6] = wkm;  j.n[6] = nW; j.f8[6] = 1;
        j.s[7] = Wv_m;  j.d[7] = wvm;  j.n[7] = nW; j.f8[7] = 1;
        j.s[8] = Wli;   j.d[8] = wli;  j.n[8] = nL; j.f8[8] = 0;
        j.s[9] = Wlm;   j.d[9] = wlm;  j.n[9] = nL; j.f8[9] = 0;
        cvt_bf<<<dim3(1024, 10), 256>>>(j);
    }

    const dim3 blk(256);
    const size_t sW  = (size_t)DIM * DIM;
    const size_t sO  = (size_t)NTOK * DIM;
    const size_t sOT = (size_t)DIM * NTOK;
    const size_t sS  = (size_t)NTOK * NTOK;
    const float scale = 0.04419417382415922f;   // 1/sqrt(512)

    // ---- projections (fp8 in!): ONE launch, 48 jobs; Q/K -> fp8, V -> fp8^T
    {
        Jobs jb;
        const uint8_t* As[6]  = {bmet, bimg, bimg, bimg, bmet, bmet};
        const uint8_t* Ws[6]  = {wqm,  wki,  wvi,  wqi,  wkm,  wvm};
        uint8_t*       Cs[6]  = {qm,   ki,   vit,  qi,   km,   vmt};
        const float*   Bs[6]  = {bq_m, bk_i, bv_i, bq_i, bk_m, bv_m};
        const int      md[6]  = {3, 3, 4, 3, 3, 4};
        for (int g = 0; g < 6; g++)
            for (int h = 0; h < NH; h++) {
                Job& J = jb.j[g * NH + h];
                J.A = (const char*)As[g];
                J.B = (const char*)(Ws[g] + (size_t)h * sW);
                J.C = (char*)(Cs[g] + (md[g] == 4 ? (size_t)h * sOT : (size_t)h * sO));
                J.bias = Bs[g] + (size_t)h * DIM;
                J.resid = nullptr; J.rowsum = nullptr;
                J.scale = 1.0f;
                J.lda = DIM; J.ldb = DIM;
                J.ldc = (md[g] == 4) ? NTOK : DIM;
                J.ldr = 0; J.outMode = md[g];
            }
        gemm_batch<1><<<dim3(DIM / 128, NTOK / 128, 48), blk, SMEM_DYN>>>(jb, DIM);
    }

    // ---- scores (fp8 in): ONE launch, 16 jobs — fp8 exp(logit) out + rowsums
    {
        Jobs jb;
        for (int p = 0; p < 2; p++)
            for (int h = 0; h < NH; h++) {
                Job& J = jb.j[p * NH + h];
                J.A = (const char*)((p ? qi : qm) + (size_t)h * sO);
                J.B = (const char*)((p ? km : ki) + (size_t)h * sO);
                J.C = (char*)((p ? pm : pi) + (size_t)h * sS);
                J.bias = nullptr; J.resid = nullptr;
                J.rowsum = rs + (size_t)(p * NH + h) * NTOK;
                J.scale = scale;
                J.lda = DIM; J.ldb = DIM; J.ldc = NTOK; J.ldr = 0; J.outMode = 5;
            }
        gemm_batch<1><<<dim3(NTOK / 128, NTOK / 128, 16), blk, SMEM_DYN>>>(jb, DIM);
    }

    // ---- AV (fp8 in): ONE launch, 16 jobs -> concat bf16, row-normalized
    {
        Jobs jb;
        for (int p = 0; p < 2; p++)
            for (int h = 0; h < NH; h++) {
                Job& J = jb.j[p * NH + h];
                J.A = (const char*)((p ? pm : pi) + (size_t)h * sS);
                J.B = (const char*)((p ? vmt : vit) + (size_t)h * sOT);
                J.C = (char*)((p ? cm : ci) + (size_t)h * DIM);
                J.bias = nullptr; J.resid = nullptr;
                J.rowsum = rs + (size_t)(p * NH + h) * NTOK;
                J.scale = 1.0f;
                J.lda = NTOK; J.ldb = NTOK; J.ldc = NH * DIM; J.ldr = 0; J.outMode = 6;
            }
        gemm_batch<1><<<dim3(DIM / 128, NTOK / 128, 16), blk, SMEM_DYN>>>(jb, NTOK);
    }

    // ---- final linears (bf16 in): ONE launch, 2 jobs, bias + fp32 residual -> d_out
    {
        Jobs jb;
        jb.j[0] = { (const char*)ci, (const char*)wli, (char*)out,
                    bli, image, nullptr, 1.0f, NH * DIM, NH * DIM, 2 * DIM, DIM, 0 };
        jb.j[1] = { (const char*)cm, (const char*)wlm, (char*)(out + DIM),
                    blm, meta,  nullptr, 1.0f, NH * DIM, NH * DIM, 2 * DIM, DIM, 0 };
        gemm_batch<0><<<dim3(DIM / 128, NTOK / 128, 2), blk, SMEM_DYN>>>(jb, NH * DIM);
    }
}